// round 12
// baseline (speedup 1.0000x reference)
#include <cuda_runtime.h>
#include <cuda_bf16.h>
#include <math.h>
#include <stdint.h>

#define T_LEN 2048
#define DIM_  1024
#define NHEAD 16
#define HD    64
#define ATTN_SCALE 0.12f

// ---------------- scratch (static device memory; no allocations) ----------------
__device__ float g_q[T_LEN * DIM_];
__device__ float g_k[T_LEN * DIM_];
__device__ float g_v[T_LEN * DIM_];
// split-bf16 operands for GEMMs: [.,0:1024)=hi, [.,1024:2048)=lo
__device__ __nv_bfloat16 g_abig[T_LEN * 2048];
__device__ __nv_bfloat16 g_ybig[T_LEN * 2048];
__device__ __nv_bfloat16 g_wt[4][1024 * 2048];
// split-bf16 q/k/v for attention (post norm+rope), layout [t][1024]
__device__ __nv_bfloat16 g_qh[T_LEN * DIM_], g_ql[T_LEN * DIM_];
__device__ __nv_bfloat16 g_kh[T_LEN * DIM_], g_kl[T_LEN * DIM_];
__device__ __nv_bfloat16 g_vh[T_LEN * DIM_], g_vl[T_LEN * DIM_];

// rotary freqs (fp32 of 2^(-2i/3), matches (1/1024)^(i/15) computed in double)
__constant__ float FREQ16[16] = {
    1.0f, 0.6299605249474366f, 0.3968502629920499f, 0.25f,
    0.15749013123685915f, 0.09921256574801247f, 0.0625f, 0.03937253280921479f,
    0.024803141437003118f, 0.015625f, 0.009843133202303698f, 0.0062007853592507794f,
    0.00390625f, 0.0024607833005759246f, 0.0015501963398126949f, 0.0009765625f
};

// ---------------- PTX helpers ----------------------------------------------------
__device__ __forceinline__ uint32_t smem_u32(const void* p) {
    uint32_t a;
    asm("{ .reg .u64 t; cvta.to.shared.u64 t, %1; cvt.u32.u64 %0, t; }" : "=r"(a) : "l"(p));
    return a;
}
__device__ __forceinline__ void mma16816(float c[4],
                                         uint32_t a0, uint32_t a1, uint32_t a2, uint32_t a3,
                                         uint32_t b0, uint32_t b1)
{
    asm volatile("mma.sync.aligned.m16n8k16.row.col.f32.bf16.bf16.f32 "
                 "{%0,%1,%2,%3}, {%4,%5,%6,%7}, {%8,%9}, {%0,%1,%2,%3};"
                 : "+f"(c[0]), "+f"(c[1]), "+f"(c[2]), "+f"(c[3])
                 : "r"(a0), "r"(a1), "r"(a2), "r"(a3), "r"(b0), "r"(b1));
}
__device__ __forceinline__ void ldm_x4(uint32_t r[4], uint32_t addr) {
    asm volatile("ldmatrix.sync.aligned.m8n8.x4.shared.b16 {%0,%1,%2,%3}, [%4];"
                 : "=r"(r[0]), "=r"(r[1]), "=r"(r[2]), "=r"(r[3]) : "r"(addr));
}
__device__ __forceinline__ void ldm_x4_t(uint32_t r[4], uint32_t addr) {
    asm volatile("ldmatrix.sync.aligned.m8n8.x4.trans.shared.b16 {%0,%1,%2,%3}, [%4];"
                 : "=r"(r[0]), "=r"(r[1]), "=r"(r[2]), "=r"(r[3]) : "r"(addr));
}
__device__ __forceinline__ uint32_t pack_bf16(__nv_bfloat16 lo, __nv_bfloat16 hi)
{
    __nv_bfloat162 t; t.x = lo; t.y = hi;
    return *(uint32_t*)&t;
}
#define CP_ASYNC16(dst, src) \
    asm volatile("cp.async.cg.shared.global [%0], [%1], 16;" :: "r"(dst), "l"(src))
#define CP_COMMIT()  asm volatile("cp.async.commit_group;" ::: "memory")
#define CP_WAIT0()   asm volatile("cp.async.wait_group 0;" ::: "memory")
#define SWZ128(o)    ((o) ^ (((o) >> 3) & 0x70))

// ---------------- split conversion (x -> hi|lo bf16) ----------------------------
__global__ __launch_bounds__(256) void split_kernel(const float* __restrict__ xin)
{
    int idx = blockIdx.x * 256 + threadIdx.x;
    float4 v = ((const float4*)xin)[idx];
    int m  = idx >> 8;
    int c0 = (idx & 255) << 2;
    __nv_bfloat16 h0 = __float2bfloat16(v.x), h1 = __float2bfloat16(v.y);
    __nv_bfloat16 h2 = __float2bfloat16(v.z), h3 = __float2bfloat16(v.w);
    __nv_bfloat16 l0 = __float2bfloat16(v.x - __bfloat162float(h0));
    __nv_bfloat16 l1 = __float2bfloat16(v.y - __bfloat162float(h1));
    __nv_bfloat16 l2 = __float2bfloat16(v.z - __bfloat162float(h2));
    __nv_bfloat16 l3 = __float2bfloat16(v.w - __bfloat162float(h3));
    __nv_bfloat16* po = g_abig + (size_t)m * 2048 + c0;
    po[0] = h0; po[1] = h1; po[2] = h2; po[3] = h3;
    po[1024] = l0; po[1025] = l1; po[1026] = l2; po[1027] = l3;
}

// ---------------- weight transpose + split: W[k][n] -> WT[n][k_hi | k_lo] -------
__global__ __launch_bounds__(256) void wconv_kernel(const float* __restrict__ Wq,
                                                    const float* __restrict__ Wk,
                                                    const float* __restrict__ Wv,
                                                    const float* __restrict__ Wo)
{
    __shared__ float tile[32][33];
    const int z = blockIdx.z;
    const float* W = (z == 0) ? Wq : (z == 1) ? Wk : (z == 2) ? Wv : Wo;
    __nv_bfloat16* WT = g_wt[z];
    const int tx = threadIdx.x & 31, ty = threadIdx.x >> 5;
    const int n  = blockIdx.x * 32 + tx;
    const int k0 = blockIdx.y * 32;
#pragma unroll
    for (int i = 0; i < 4; i++)
        tile[ty + i * 8][tx] = W[(size_t)(k0 + ty + i * 8) * 1024 + n];
    __syncthreads();
#pragma unroll
    for (int i = 0; i < 4; i++) {
        float v = tile[tx][ty + i * 8];
        __nv_bfloat16 hi = __float2bfloat16(v);
        __nv_bfloat16 lo = __float2bfloat16(v - __bfloat162float(hi));
        size_t base = (size_t)(blockIdx.x * 32 + ty + i * 8) * 2048 + k0 + tx;
        WT[base]        = hi;
        WT[base + 1024] = lo;
    }
}

// ---------------- raw-mma split-bf16 GEMM v2: 64x64 warp tile -------------------
// CTA 128x128, 128 thr / 4 warps (2m x 2n). LDSM/MMA = 0.25. 2-stage cp.async
// (64KB smem) -> 3 CTAs/SM; QKV's 384 CTAs fit one wave.
#define GEMM_NCHUNK 48
#define G2_STAGE 32768
#define GEMM_SMEM (2 * G2_STAGE)

__global__ __launch_bounds__(128, 3) void gemm_mma(int proj, float* __restrict__ outp)
{
    extern __shared__ char smg[];
    const uint32_t sbase = smem_u32(smg);
    const int tid  = threadIdx.x;
    const int wid  = tid >> 5;
    const int lane = tid & 31;
    const int n0 = blockIdx.x * 128;
    const int m0 = blockIdx.y * 128;
    const int z  = blockIdx.z;

    const __nv_bfloat16* A  = proj ? g_ybig : g_abig;
    const __nv_bfloat16* Bt = proj ? g_wt[3] : g_wt[z];
    float* C = proj ? outp : (z == 0 ? g_q : z == 1 ? g_k : g_v);

    const __nv_bfloat16* Ag = A  + (size_t)m0 * 2048;
    const __nv_bfloat16* Bg = Bt + (size_t)n0 * 2048;

    const int wm = wid >> 1;          // 0..1 -> m offset wm*64
    const int wn = wid & 1;           // 0..1 -> n offset wn*64
    const int quad = lane >> 3;
    const int r8   = lane & 7;

    float acc[4][8][4];
#pragma unroll
    for (int i = 0; i < 4; i++)
#pragma unroll
        for (int f = 0; f < 8; f++)
#pragma unroll
            for (int q = 0; q < 4; q++) acc[i][f][q] = 0.0f;

    // chunk loader: A 128x64 bf16 (16KB) + B 128x64 (16KB), 16 granules/thread
    auto load_chunk = [&](int cn) {
        const int part = cn >> 4, sub = cn & 15;
        const int ka = (part == 2 ? 1024 : 0) + sub * 64;   // A: hi,hi,lo
        const int kb = (part == 1 ? 1024 : 0) + sub * 64;   // B: hi,lo,hi
        const uint32_t As = sbase + (cn & 1) * G2_STAGE;
        const uint32_t Bs = As + 16384;
#pragma unroll
        for (int s = 0; s < 8; s++) {
            const int idx = tid + s * 128;
            const int row = idx >> 3, g = idx & 7;
            const uint32_t off = SWZ128((uint32_t)(row * 128 + g * 16));
            CP_ASYNC16(As + off, (const void*)(Ag + (size_t)row * 2048 + ka + g * 8));
            CP_ASYNC16(Bs + off, (const void*)(Bg + (size_t)row * 2048 + kb + g * 8));
        }
        CP_COMMIT();
    };

    load_chunk(0);

    for (int c = 0; c < GEMM_NCHUNK; c++) {
        CP_WAIT0();
        __syncthreads();
        if (c + 1 < GEMM_NCHUNK) load_chunk(c + 1);

        const uint32_t As = sbase + (c & 1) * G2_STAGE;
        const uint32_t Bs = As + 16384;
#pragma unroll
        for (int ks = 0; ks < 4; ks++) {
            uint32_t a[4][4];
#pragma unroll
            for (int i = 0; i < 4; i++) {
                const int row = wm * 64 + i * 16 + r8 + (quad & 1) * 8;
                const int cb  = ks * 32 + (quad >> 1) * 16;
                ldm_x4(a[i], As + SWZ128((uint32_t)(row * 128 + cb)));
            }
#pragma unroll
            for (int j = 0; j < 4; j++) {
                uint32_t b[4];
                const int row = wn * 64 + j * 16 + r8 + (quad >> 1) * 8;
                const int cb  = ks * 32 + (quad & 1) * 16;
                ldm_x4(b, Bs + SWZ128((uint32_t)(row * 128 + cb)));
#pragma unroll
                for (int i = 0; i < 4; i++) {
                    mma16816(acc[i][2 * j],     a[i][0], a[i][1], a[i][2], a[i][3], b[0], b[1]);
                    mma16816(acc[i][2 * j + 1], a[i][0], a[i][1], a[i][2], a[i][3], b[2], b[3]);
                }
            }
        }
    }

    // epilogue: C fragments -> global fp32
    const int erow  = lane >> 2;
    const int ecol2 = (lane & 3) * 2;
#pragma unroll
    for (int i = 0; i < 4; i++)
#pragma unroll
        for (int f = 0; f < 8; f++) {
            float* p0 = C + (size_t)(m0 + wm * 64 + i * 16 + erow) * 1024
                          + n0 + wn * 64 + f * 8 + ecol2;
            *(float2*)p0            = make_float2(acc[i][f][0], acc[i][f][1]);
            *(float2*)(p0 + 8*1024) = make_float2(acc[i][f][2], acc[i][f][3]);
        }
}

// ---------------- cosine-norm + scale + rotary + bf16 split ---------------------
__global__ __launch_bounds__(512) void normrope_kernel(const float* __restrict__ s_qk)
{
    const int t    = blockIdx.x;
    const int h    = threadIdx.x >> 5;
    const int lane = threadIdx.x & 31;

    float c, s;
    if (lane < 16) {
        float theta = (float)t * FREQ16[lane];
        sincosf(theta, &s, &c);
    } else { c = 1.0f; s = 0.0f; }

    const float sc1 = s_qk[h * HD + lane]      * 32.0f;
    const float sc2 = s_qk[h * HD + lane + 32] * 32.0f;

    const size_t base = (size_t)t * DIM_ + h * HD;

    const float* inp[2] = {g_q + base, g_k + base};
    __nv_bfloat16* oh[2] = {g_qh + base, g_kh + base};
    __nv_bfloat16* ol[2] = {g_ql + base, g_kl + base};
#pragma unroll
    for (int w = 0; w < 2; w++) {
        const float* p = inp[w];
        float v1 = p[lane];
        float v2 = p[lane + 32];
        float ss = v1 * v1 + v2 * v2;
#pragma unroll
        for (int o = 16; o > 0; o >>= 1)
            ss += __shfl_xor_sync(0xffffffffu, ss, o);
        float rn = rsqrtf(ss + 1e-12f);
        v1 *= rn * sc1;
        v2 *= rn * sc2;
        float y1 = v1 * c + v2 * s;
        float y2 = v2 * c - v1 * s;
        __nv_bfloat16 h1 = __float2bfloat16(y1);
        __nv_bfloat16 h2 = __float2bfloat16(y2);
        oh[w][lane]      = h1;
        oh[w][lane + 32] = h2;
        ol[w][lane]      = __float2bfloat16(y1 - __bfloat162float(h1));
        ol[w][lane + 32] = __float2bfloat16(y2 - __bfloat162float(h2));
    }
    {
        float v1 = g_v[base + lane];
        float v2 = g_v[base + lane + 32];
        __nv_bfloat16 h1 = __float2bfloat16(v1);
        __nv_bfloat16 h2 = __float2bfloat16(v2);
        g_vh[base + lane]      = h1;
        g_vh[base + lane + 32] = h2;
        g_vl[base + lane]      = __float2bfloat16(v1 - __bfloat162float(h1));
        g_vl[base + lane + 32] = __float2bfloat16(v2 - __bfloat162float(h2));
    }
}

// ---------------- pipelined flash attention (R11, passing) ----------------------
#define ATT_STAGE 32768
#define ATT_SMEM  (2 * ATT_STAGE)

__global__ __launch_bounds__(128) void attn_mma()
{
    extern __shared__ char sma[];
    const uint32_t sbase = smem_u32(sma);

    const int qb   = 31 - (int)blockIdx.x;
    const int h    = blockIdx.y;
    const int tid  = threadIdx.x;
    const int wid  = tid >> 5;
    const int lane = tid & 31;
    const int lr   = lane >> 2;
    const int lc   = lane & 3;

    const __nv_bfloat16* GKh0 = g_kh + h * HD;
    const __nv_bfloat16* GKl0 = g_kl + h * HD;
    const __nv_bfloat16* GVh0 = g_vh + h * HD;
    const __nv_bfloat16* GVl0 = g_vl + h * HD;

    auto load_tiles = [&](int kb, int stage) {
        const uint32_t sb = sbase + stage * ATT_STAGE;
        const size_t gbase = (size_t)(kb * 64) * DIM_;
#pragma unroll
        for (int i = 0; i < 4; i++) {
            const int idx = tid + i * 128;
            const int row = idx >> 3, g = idx & 7;
            const uint32_t off = SWZ128((uint32_t)(row * 128 + g * 16));
            const size_t goff = gbase + (size_t)row * DIM_ + g * 8;
            CP_ASYNC16(sb + off,          (const void*)(GKh0 + goff));
            CP_ASYNC16(sb + 8192 + off,   (const void*)(GKl0 + goff));
            CP_ASYNC16(sb + 16384 + off,  (const void*)(GVh0 + goff));
            CP_ASYNC16(sb + 24576 + off,  (const void*)(GVl0 + goff));
        }
        CP_COMMIT();
    };

    const size_t qrow0 = (size_t)(qb * 64 + wid * 16 + lr) * DIM_ + h * HD;
    const size_t qrow8 = qrow0 + 8 * DIM_;
    uint32_t qa_h[4][4], qa_l[4][4];
#pragma unroll
    for (int t = 0; t < 4; t++) {
        const int c0 = t * 16 + 2 * lc;
        qa_h[t][0] = *(const uint32_t*)(g_qh + qrow0 + c0);
        qa_h[t][1] = *(const uint32_t*)(g_qh + qrow8 + c0);
        qa_h[t][2] = *(const uint32_t*)(g_qh + qrow0 + c0 + 8);
        qa_h[t][3] = *(const uint32_t*)(g_qh + qrow8 + c0 + 8);
        qa_l[t][0] = *(const uint32_t*)(g_ql + qrow0 + c0);
        qa_l[t][1] = *(const uint32_t*)(g_ql + qrow8 + c0);
        qa_l[t][2] = *(const uint32_t*)(g_ql + qrow0 + c0 + 8);
        qa_l[t][3] = *(const uint32_t*)(g_ql + qrow8 + c0 + 8);
    }

    load_tiles(0, 0);

    float ofr[8][4];
#pragma unroll
    for (int j = 0; j < 8; j++)
#pragma unroll
        for (int q = 0; q < 4; q++) ofr[j][q] = 0.0f;
    float m0 = -1e30f, m1 = -1e30f, l0 = 0.0f, l1 = 0.0f;

    const int gr0 = qb * 64 + wid * 16 + lr;
    const int gr8 = gr0 + 8;

    const int l7  = lane & 7;
    const int lk8 = (lane >> 4) * 8;
    const int ld8 = ((lane >> 3) & 1) * 8;

    for (int kb = 0; kb <= qb; kb++) {
        CP_WAIT0();
        __syncthreads();
        if (kb < qb) load_tiles(kb + 1, (kb + 1) & 1);

        const uint32_t sb  = sbase + (kb & 1) * ATT_STAGE;
        const uint32_t Khs = sb;
        const uint32_t Kls = sb + 8192;
        const uint32_t Vhs = sb + 16384;
        const uint32_t Vls = sb + 24576;

        float sfr[8][4];
#pragma unroll
        for (int j = 0; j < 8; j++)
#pragma unroll
            for (int q = 0; q < 4; q++) sfr[j][q] = 0.0f;

#pragma unroll
        for (int t = 0; t < 4; t++) {
#pragma unroll
            for (int jp = 0; jp < 4; jp++) {
                const uint32_t off = SWZ128((uint32_t)((jp * 16 + lk8 + l7) * 128
                                                       + (t * 16 + ld8) * 2));
                uint32_t kh[4], kl[4];
                ldm_x4(kh, Khs + off);
                ldm_x4(kl, Kls + off);
                mma16816(sfr[2*jp],   qa_h[t][0], qa_h[t][1], qa_h[t][2], qa_h[t][3], kh[0], kh[1]);
                mma16816(sfr[2*jp],   qa_h[t][0], qa_h[t][1], qa_h[t][2], qa_h[t][3], kl[0], kl[1]);
                mma16816(sfr[2*jp],   qa_l[t][0], qa_l[t][1], qa_l[t][2], qa_l[t][3], kh[0], kh[1]);
                mma16816(sfr[2*jp+1], qa_h[t][0], qa_h[t][1], qa_h[t][2], qa_h[t][3], kh[2], kh[3]);
                mma16816(sfr[2*jp+1], qa_h[t][0], qa_h[t][1], qa_h[t][2], qa_h[t][3], kl[2], kl[3]);
                mma16816(sfr[2*jp+1], qa_l[t][0], qa_l[t][1], qa_l[t][2], qa_l[t][3], kh[2], kh[3]);
            }
        }

        const bool diag = (kb == qb);
#pragma unroll
        for (int j = 0; j < 8; j++) {
            const int gc = kb * 64 + j * 8 + 2 * lc;
            float v0 = sfr[j][0] * ATTN_SCALE;
            float v1 = sfr[j][1] * ATTN_SCALE;
            float v2 = sfr[j][2] * ATTN_SCALE;
            float v3 = sfr[j][3] * ATTN_SCALE;
            if (diag) {
                if (gc     > gr0) v0 = -1e30f;
                if (gc + 1 > gr0) v1 = -1e30f;
                if (gc     > gr8) v2 = -1e30f;
                if (gc + 1 > gr8) v3 = -1e30f;
            }
            sfr[j][0] = v0; sfr[j][1] = v1; sfr[j][2] = v2; sfr[j][3] = v3;
        }

        float mx0 = -1e30f, mx1 = -1e30f;
#pragma unroll
        for (int j = 0; j < 8; j++) {
            mx0 = fmaxf(mx0, fmaxf(sfr[j][0], sfr[j][1]));
            mx1 = fmaxf(mx1, fmaxf(sfr[j][2], sfr[j][3]));
        }
        mx0 = fmaxf(mx0, __shfl_xor_sync(0xffffffffu, mx0, 1));
        mx0 = fmaxf(mx0, __shfl_xor_sync(0xffffffffu, mx0, 2));
        mx1 = fmaxf(mx1, __shfl_xor_sync(0xffffffffu, mx1, 1));
        mx1 = fmaxf(mx1, __shfl_xor_sync(0xffffffffu, mx1, 2));
        const float mn0 = fmaxf(m0, mx0);
        const float mn1 = fmaxf(m1, mx1);
        const float cor0 = __expf(m0 - mn0);
        const float cor1 = __expf(m1 - mn1);
        m0 = mn0; m1 = mn1;
        float s0 = 0.0f, s1 = 0.0f;
#pragma unroll
        for (int j = 0; j < 8; j++) {
            sfr[j][0] = __expf(sfr[j][0] - mn0);
            sfr[j][1] = __expf(sfr[j][1] - mn0);
            sfr[j][2] = __expf(sfr[j][2] - mn1);
            sfr[j][3] = __expf(sfr[j][3] - mn1);
            s0 += sfr[j][0] + sfr[j][1];
            s1 += sfr[j][2] + sfr[j][3];
        }
        s0 += __shfl_xor_sync(0xffffffffu, s0, 1);
        s0 += __shfl_xor_sync(0xffffffffu, s0, 2);
        s1 += __shfl_xor_sync(0xffffffffu, s1, 1);
        s1 += __shfl_xor_sync(0xffffffffu, s1, 2);
        l0 = l0 * cor0 + s0;
        l1 = l1 * cor1 + s1;

#pragma unroll
        for (int j = 0; j < 8; j++) {
            ofr[j][0] *= cor0; ofr[j][1] *= cor0;
            ofr[j][2] *= cor1; ofr[j][3] *= cor1;
        }

#pragma unroll
        for (int u = 0; u < 4; u++) {
            __nv_bfloat16 b00 = __float2bfloat16(sfr[2*u][0]);
            __nv_bfloat16 b01 = __float2bfloat16(sfr[2*u][1]);
            __nv_bfloat16 b02 = __float2bfloat16(sfr[2*u][2]);
            __nv_bfloat16 b03 = __float2bfloat16(sfr[2*u][3]);
            __nv_bfloat16 b10 = __float2bfloat16(sfr[2*u+1][0]);
            __nv_bfloat16 b11 = __float2bfloat16(sfr[2*u+1][1]);
            __nv_bfloat16 b12 = __float2bfloat16(sfr[2*u+1][2]);
            __nv_bfloat16 b13 = __float2bfloat16(sfr[2*u+1][3]);
            uint32_t pah0 = pack_bf16(b00, b01);
            uint32_t pah1 = pack_bf16(b02, b03);
            uint32_t pah2 = pack_bf16(b10, b11);
            uint32_t pah3 = pack_bf16(b12, b13);
            uint32_t pal0 = pack_bf16(__float2bfloat16(sfr[2*u][0]   - __bfloat162float(b00)),
                                      __float2bfloat16(sfr[2*u][1]   - __bfloat162float(b01)));
            uint32_t pal1 = pack_bf16(__float2bfloat16(sfr[2*u][2]   - __bfloat162float(b02)),
                                      __float2bfloat16(sfr[2*u][3]   - __bfloat162float(b03)));
            uint32_t pal2 = pack_bf16(__float2bfloat16(sfr[2*u+1][0] - __bfloat162float(b10)),
                                      __float2bfloat16(sfr[2*u+1][1] - __bfloat162float(b11)));
            uint32_t pal3 = pack_bf16(__float2bfloat16(sfr[2*u+1][2] - __bfloat162float(b12)),
                                      __float2bfloat16(sfr[2*u+1][3] - __bfloat162float(b13)));
#pragma unroll
            for (int jp = 0; jp < 4; jp++) {
                const uint32_t off = SWZ128((uint32_t)((u * 16 + ld8 + l7) * 128
                                                       + (jp * 16 + lk8) * 2));
                uint32_t vh[4], vl[4];
                ldm_x4_t(vh, Vhs + off);
                ldm_x4_t(vl, Vls + off);
                mma16816(ofr[2*jp],   pah0, pah1, pah2, pah3, vh[0], vh[1]);
                mma16816(ofr[2*jp],   pah0, pah1, pah2, pah3, vl[0], vl[1]);
                mma16816(ofr[2*jp],   pal0, pal1, pal2, pal3, vh[0], vh[1]);
                mma16816(ofr[2*jp+1], pah0, pah1, pah2, pah3, vh[2], vh[3]);
                mma16816(ofr[2*jp+1], pah0, pah1, pah2, pah3, vl[2], vl[3]);
                mma16816(ofr[2*jp+1], pal0, pal1, pal2, pal3, vh[2], vh[3]);
            }
        }
    }

    const float inv0 = 1.0f / l0;
    const float inv1 = 1.0f / l1;
    __nv_bfloat16* Y0 = g_ybig + (size_t)gr0 * 2048 + h * HD;
    __nv_bfloat16* Y8 = g_ybig + (size_t)gr8 * 2048 + h * HD;
#pragma unroll
    for (int j2 = 0; j2 < 8; j2++) {
        const int cc = j2 * 8 + 2 * lc;
        float y0 = ofr[j2][0] * inv0, y1 = ofr[j2][1] * inv0;
        float y2 = ofr[j2][2] * inv1, y3 = ofr[j2][3] * inv1;
        __nv_bfloat16 h0 = __float2bfloat16(y0), h1 = __float2bfloat16(y1);
        __nv_bfloat16 h2 = __float2bfloat16(y2), h3 = __float2bfloat16(y3);
        *(uint32_t*)(Y0 + cc)        = pack_bf16(h0, h1);
        *(uint32_t*)(Y8 + cc)        = pack_bf16(h2, h3);
        *(uint32_t*)(Y0 + 1024 + cc) = pack_bf16(__float2bfloat16(y0 - __bfloat162float(h0)),
                                                 __float2bfloat16(y1 - __bfloat162float(h1)));
        *(uint32_t*)(Y8 + 1024 + cc) = pack_bf16(__float2bfloat16(y2 - __bfloat162float(h2)),
                                                 __float2bfloat16(y3 - __bfloat162float(h3)));
    }
}

// ---------------- launcher ------------------------------------------------------
extern "C" void kernel_launch(void* const* d_in, const int* in_sizes, int n_in,
                              void* d_out, int out_size)
{
    const float* x    = (const float*)d_in[0];
    const float* Wq   = (const float*)d_in[1];
    const float* Wk   = (const float*)d_in[2];
    const float* Wv   = (const float*)d_in[3];
    const float* Wo   = (const float*)d_in[4];
    const float* s_qk = (const float*)d_in[5];
    float* out = (float*)d_out;

    cudaFuncSetAttribute(gemm_mma, cudaFuncAttributeMaxDynamicSharedMemorySize,
                         GEMM_SMEM);
    cudaFuncSetAttribute(attn_mma, cudaFuncAttributeMaxDynamicSharedMemorySize,
                         ATT_SMEM);

    // operand prep
    split_kernel<<<2048, 256>>>(x);
    wconv_kernel<<<dim3(32, 32, 4), 256>>>(Wq, Wk, Wv, Wo);

    // QKV projections (split-bf16, logical K'=3072) — 64x64 warp tile, 3 CTA/SM
    gemm_mma<<<dim3(8, 16, 3), 128, GEMM_SMEM>>>(0, nullptr);

    // norm + rope + bf16 split for attention
    normrope_kernel<<<T_LEN, 512>>>(s_qk);

    // pipelined flash attention (epilogue feeds g_ybig directly)
    attn_mma<<<dim3(32, NHEAD), 128, ATT_SMEM>>>();

    // output projection
    gemm_mma<<<dim3(8, 16, 1), 128, GEMM_SMEM>>>(1, out);
}

// round 13
// speedup vs baseline: 1.1149x; 1.1149x over previous
#include <cuda_runtime.h>
#include <cuda_bf16.h>
#include <math.h>
#include <stdint.h>

#define T_LEN 2048
#define DIM_  1024
#define NHEAD 16
#define HD    64
#define ATTN_SCALE 0.12f

// ---------------- scratch (static device memory; no allocations) ----------------
__device__ float g_q[T_LEN * DIM_];
__device__ float g_k[T_LEN * DIM_];
__device__ float g_v[T_LEN * DIM_];
// split-bf16 operands for GEMMs: [.,0:1024)=hi, [.,1024:2048)=lo
__device__ __nv_bfloat16 g_abig[T_LEN * 2048];
__device__ __nv_bfloat16 g_ybig[T_LEN * 2048];
__device__ __nv_bfloat16 g_wt[4][1024 * 2048];
// split-bf16 q/k/v for attention (post norm+rope), layout [t][1024]
__device__ __nv_bfloat16 g_qh[T_LEN * DIM_], g_ql[T_LEN * DIM_];
__device__ __nv_bfloat16 g_kh[T_LEN * DIM_], g_kl[T_LEN * DIM_];
__device__ __nv_bfloat16 g_vh[T_LEN * DIM_], g_vl[T_LEN * DIM_];

// rotary freqs (fp32 of 2^(-2i/3), matches (1/1024)^(i/15) computed in double)
__constant__ float FREQ16[16] = {
    1.0f, 0.6299605249474366f, 0.3968502629920499f, 0.25f,
    0.15749013123685915f, 0.09921256574801247f, 0.0625f, 0.03937253280921479f,
    0.024803141437003118f, 0.015625f, 0.009843133202303698f, 0.0062007853592507794f,
    0.00390625f, 0.0024607833005759246f, 0.0015501963398126949f, 0.0009765625f
};

// ---------------- PTX helpers ----------------------------------------------------
__device__ __forceinline__ uint32_t smem_u32(const void* p) {
    uint32_t a;
    asm("{ .reg .u64 t; cvta.to.shared.u64 t, %1; cvt.u32.u64 %0, t; }" : "=r"(a) : "l"(p));
    return a;
}
__device__ __forceinline__ void mma16816(float c[4],
                                         uint32_t a0, uint32_t a1, uint32_t a2, uint32_t a3,
                                         uint32_t b0, uint32_t b1)
{
    asm volatile("mma.sync.aligned.m16n8k16.row.col.f32.bf16.bf16.f32 "
                 "{%0,%1,%2,%3}, {%4,%5,%6,%7}, {%8,%9}, {%0,%1,%2,%3};"
                 : "+f"(c[0]), "+f"(c[1]), "+f"(c[2]), "+f"(c[3])
                 : "r"(a0), "r"(a1), "r"(a2), "r"(a3), "r"(b0), "r"(b1));
}
__device__ __forceinline__ void ldm_x4(uint32_t r[4], uint32_t addr) {
    asm volatile("ldmatrix.sync.aligned.m8n8.x4.shared.b16 {%0,%1,%2,%3}, [%4];"
                 : "=r"(r[0]), "=r"(r[1]), "=r"(r[2]), "=r"(r[3]) : "r"(addr));
}
__device__ __forceinline__ void ldm_x4_t(uint32_t r[4], uint32_t addr) {
    asm volatile("ldmatrix.sync.aligned.m8n8.x4.trans.shared.b16 {%0,%1,%2,%3}, [%4];"
                 : "=r"(r[0]), "=r"(r[1]), "=r"(r[2]), "=r"(r[3]) : "r"(addr));
}
__device__ __forceinline__ uint32_t pack_bf16(__nv_bfloat16 lo, __nv_bfloat16 hi)
{
    __nv_bfloat162 t; t.x = lo; t.y = hi;
    return *(uint32_t*)&t;
}
#define CP_ASYNC16(dst, src) \
    asm volatile("cp.async.cg.shared.global [%0], [%1], 16;" :: "r"(dst), "l"(src))
#define CP_COMMIT()  asm volatile("cp.async.commit_group;" ::: "memory")
#define CP_WAIT1()   asm volatile("cp.async.wait_group 1;" ::: "memory")
#define CP_WAIT0()   asm volatile("cp.async.wait_group 0;" ::: "memory")
#define SWZ128(o)    ((o) ^ (((o) >> 3) & 0x70))

// ---------------- split conversion (x -> hi|lo bf16) ----------------------------
__global__ __launch_bounds__(256) void split_kernel(const float* __restrict__ xin)
{
    int idx = blockIdx.x * 256 + threadIdx.x;
    float4 v = ((const float4*)xin)[idx];
    int m  = idx >> 8;
    int c0 = (idx & 255) << 2;
    __nv_bfloat16 h0 = __float2bfloat16(v.x), h1 = __float2bfloat16(v.y);
    __nv_bfloat16 h2 = __float2bfloat16(v.z), h3 = __float2bfloat16(v.w);
    __nv_bfloat16 l0 = __float2bfloat16(v.x - __bfloat162float(h0));
    __nv_bfloat16 l1 = __float2bfloat16(v.y - __bfloat162float(h1));
    __nv_bfloat16 l2 = __float2bfloat16(v.z - __bfloat162float(h2));
    __nv_bfloat16 l3 = __float2bfloat16(v.w - __bfloat162float(h3));
    __nv_bfloat16* po = g_abig + (size_t)m * 2048 + c0;
    po[0] = h0; po[1] = h1; po[2] = h2; po[3] = h3;
    po[1024] = l0; po[1025] = l1; po[1026] = l2; po[1027] = l3;
}

// ---------------- weight transpose + split: W[k][n] -> WT[n][k_hi | k_lo] -------
__global__ __launch_bounds__(256) void wconv_kernel(const float* __restrict__ Wq,
                                                    const float* __restrict__ Wk,
                                                    const float* __restrict__ Wv,
                                                    const float* __restrict__ Wo)
{
    __shared__ float tile[32][33];
    const int z = blockIdx.z;
    const float* W = (z == 0) ? Wq : (z == 1) ? Wk : (z == 2) ? Wv : Wo;
    __nv_bfloat16* WT = g_wt[z];
    const int tx = threadIdx.x & 31, ty = threadIdx.x >> 5;
    const int n  = blockIdx.x * 32 + tx;
    const int k0 = blockIdx.y * 32;
#pragma unroll
    for (int i = 0; i < 4; i++)
        tile[ty + i * 8][tx] = W[(size_t)(k0 + ty + i * 8) * 1024 + n];
    __syncthreads();
#pragma unroll
    for (int i = 0; i < 4; i++) {
        float v = tile[tx][ty + i * 8];
        __nv_bfloat16 hi = __float2bfloat16(v);
        __nv_bfloat16 lo = __float2bfloat16(v - __bfloat162float(hi));
        size_t base = (size_t)(blockIdx.x * 32 + ty + i * 8) * 2048 + k0 + tx;
        WT[base]        = hi;
        WT[base + 1024] = lo;
    }
}

// ---------------- raw-mma split-bf16 GEMM v3: 64x64 warp tile, 3-stage ----------
// CTA 128x128, 128 thr / 4 warps (2m x 2n). LDSM/MMA = 0.25.
// 3-stage cp.async (96KB smem), launch_bounds(128,2) -> 256 regs, NO spills.
#define GEMM_NCHUNK 48
#define GSTAGES 3
#define STAGE_BYTES 32768
#define GEMM_SMEM (GSTAGES * STAGE_BYTES)

__global__ __launch_bounds__(128, 2) void gemm_mma(int proj, float* __restrict__ outp)
{
    extern __shared__ char smg[];
    const uint32_t sbase = smem_u32(smg);
    const int tid  = threadIdx.x;
    const int wid  = tid >> 5;
    const int lane = tid & 31;
    const int n0 = blockIdx.x * 128;
    const int m0 = blockIdx.y * 128;
    const int z  = blockIdx.z;

    const __nv_bfloat16* A  = proj ? g_ybig : g_abig;
    const __nv_bfloat16* Bt = proj ? g_wt[3] : g_wt[z];
    float* C = proj ? outp : (z == 0 ? g_q : z == 1 ? g_k : g_v);

    const __nv_bfloat16* Ag = A  + (size_t)m0 * 2048;
    const __nv_bfloat16* Bg = Bt + (size_t)n0 * 2048;

    const int wm = wid >> 1;          // 0..1 -> m offset wm*64
    const int wn = wid & 1;           // 0..1 -> n offset wn*64
    const int quad = lane >> 3;
    const int r8   = lane & 7;

    float acc[4][8][4];
#pragma unroll
    for (int i = 0; i < 4; i++)
#pragma unroll
        for (int f = 0; f < 8; f++)
#pragma unroll
            for (int q = 0; q < 4; q++) acc[i][f][q] = 0.0f;

    // chunk loader: A 128x64 bf16 (16KB) + B 128x64 (16KB), 16 granules/thread
    auto load_chunk = [&](int cn) {
        const int part = cn >> 4, sub = cn & 15;
        const int ka = (part == 2 ? 1024 : 0) + sub * 64;   // A: hi,hi,lo
        const int kb = (part == 1 ? 1024 : 0) + sub * 64;   // B: hi,lo,hi
        const uint32_t As = sbase + (cn % GSTAGES) * STAGE_BYTES;
        const uint32_t Bs = As + 16384;
#pragma unroll
        for (int s = 0; s < 8; s++) {
            const int idx = tid + s * 128;
            const int row = idx >> 3, g = idx & 7;
            const uint32_t off = SWZ128((uint32_t)(row * 128 + g * 16));
            CP_ASYNC16(As + off, (const void*)(Ag + (size_t)row * 2048 + ka + g * 8));
            CP_ASYNC16(Bs + off, (const void*)(Bg + (size_t)row * 2048 + kb + g * 8));
        }
        CP_COMMIT();
    };

    load_chunk(0);
    load_chunk(1);

    for (int c = 0; c < GEMM_NCHUNK; c++) {
        if (c == GEMM_NCHUNK - 1) CP_WAIT0(); else CP_WAIT1();
        __syncthreads();                       // chunk c visible; stage (c-1)%3 free
        if (c + 2 < GEMM_NCHUNK) load_chunk(c + 2);

        const uint32_t As = sbase + (c % GSTAGES) * STAGE_BYTES;
        const uint32_t Bs = As + 16384;
#pragma unroll
        for (int ks = 0; ks < 4; ks++) {
            uint32_t a[4][4];
#pragma unroll
            for (int i = 0; i < 4; i++) {
                const int row = wm * 64 + i * 16 + r8 + (quad & 1) * 8;
                const int cb  = ks * 32 + (quad >> 1) * 16;
                ldm_x4(a[i], As + SWZ128((uint32_t)(row * 128 + cb)));
            }
#pragma unroll
            for (int j = 0; j < 4; j++) {
                uint32_t b[4];
                const int row = wn * 64 + j * 16 + r8 + (quad >> 1) * 8;
                const int cb  = ks * 32 + (quad & 1) * 16;
                ldm_x4(b, Bs + SWZ128((uint32_t)(row * 128 + cb)));
#pragma unroll
                for (int i = 0; i < 4; i++) {
                    mma16816(acc[i][2 * j],     a[i][0], a[i][1], a[i][2], a[i][3], b[0], b[1]);
                    mma16816(acc[i][2 * j + 1], a[i][0], a[i][1], a[i][2], a[i][3], b[2], b[3]);
                }
            }
        }
    }

    // epilogue: C fragments -> global fp32
    const int erow  = lane >> 2;
    const int ecol2 = (lane & 3) * 2;
#pragma unroll
    for (int i = 0; i < 4; i++)
#pragma unroll
        for (int f = 0; f < 8; f++) {
            float* p0 = C + (size_t)(m0 + wm * 64 + i * 16 + erow) * 1024
                          + n0 + wn * 64 + f * 8 + ecol2;
            *(float2*)p0            = make_float2(acc[i][f][0], acc[i][f][1]);
            *(float2*)(p0 + 8*1024) = make_float2(acc[i][f][2], acc[i][f][3]);
        }
}

// ---------------- cosine-norm + scale + rotary + bf16 split ---------------------
__global__ __launch_bounds__(512) void normrope_kernel(const float* __restrict__ s_qk)
{
    const int t    = blockIdx.x;
    const int h    = threadIdx.x >> 5;
    const int lane = threadIdx.x & 31;

    float c, s;
    if (lane < 16) {
        float theta = (float)t * FREQ16[lane];
        sincosf(theta, &s, &c);
    } else { c = 1.0f; s = 0.0f; }

    const float sc1 = s_qk[h * HD + lane]      * 32.0f;
    const float sc2 = s_qk[h * HD + lane + 32] * 32.0f;

    const size_t base = (size_t)t * DIM_ + h * HD;

    const float* inp[2] = {g_q + base, g_k + base};
    __nv_bfloat16* oh[2] = {g_qh + base, g_kh + base};
    __nv_bfloat16* ol[2] = {g_ql + base, g_kl + base};
#pragma unroll
    for (int w = 0; w < 2; w++) {
        const float* p = inp[w];
        float v1 = p[lane];
        float v2 = p[lane + 32];
        float ss = v1 * v1 + v2 * v2;
#pragma unroll
        for (int o = 16; o > 0; o >>= 1)
            ss += __shfl_xor_sync(0xffffffffu, ss, o);
        float rn = rsqrtf(ss + 1e-12f);
        v1 *= rn * sc1;
        v2 *= rn * sc2;
        float y1 = v1 * c + v2 * s;
        float y2 = v2 * c - v1 * s;
        __nv_bfloat16 h1 = __float2bfloat16(y1);
        __nv_bfloat16 h2 = __float2bfloat16(y2);
        oh[w][lane]      = h1;
        oh[w][lane + 32] = h2;
        ol[w][lane]      = __float2bfloat16(y1 - __bfloat162float(h1));
        ol[w][lane + 32] = __float2bfloat16(y2 - __bfloat162float(h2));
    }
    {
        float v1 = g_v[base + lane];
        float v2 = g_v[base + lane + 32];
        __nv_bfloat16 h1 = __float2bfloat16(v1);
        __nv_bfloat16 h2 = __float2bfloat16(v2);
        g_vh[base + lane]      = h1;
        g_vh[base + lane + 32] = h2;
        g_vl[base + lane]      = __float2bfloat16(v1 - __bfloat162float(h1));
        g_vl[base + lane + 32] = __float2bfloat16(v2 - __bfloat162float(h2));
    }
}

// ---------------- pipelined flash attention (R11, passing) ----------------------
#define ATT_STAGE 32768
#define ATT_SMEM  (2 * ATT_STAGE)

__global__ __launch_bounds__(128) void attn_mma()
{
    extern __shared__ char sma[];
    const uint32_t sbase = smem_u32(sma);

    const int qb   = 31 - (int)blockIdx.x;
    const int h    = blockIdx.y;
    const int tid  = threadIdx.x;
    const int wid  = tid >> 5;
    const int lane = tid & 31;
    const int lr   = lane >> 2;
    const int lc   = lane & 3;

    const __nv_bfloat16* GKh0 = g_kh + h * HD;
    const __nv_bfloat16* GKl0 = g_kl + h * HD;
    const __nv_bfloat16* GVh0 = g_vh + h * HD;
    const __nv_bfloat16* GVl0 = g_vl + h * HD;

    auto load_tiles = [&](int kb, int stage) {
        const uint32_t sb = sbase + stage * ATT_STAGE;
        const size_t gbase = (size_t)(kb * 64) * DIM_;
#pragma unroll
        for (int i = 0; i < 4; i++) {
            const int idx = tid + i * 128;
            const int row = idx >> 3, g = idx & 7;
            const uint32_t off = SWZ128((uint32_t)(row * 128 + g * 16));
            const size_t goff = gbase + (size_t)row * DIM_ + g * 8;
            CP_ASYNC16(sb + off,          (const void*)(GKh0 + goff));
            CP_ASYNC16(sb + 8192 + off,   (const void*)(GKl0 + goff));
            CP_ASYNC16(sb + 16384 + off,  (const void*)(GVh0 + goff));
            CP_ASYNC16(sb + 24576 + off,  (const void*)(GVl0 + goff));
        }
        CP_COMMIT();
    };

    const size_t qrow0 = (size_t)(qb * 64 + wid * 16 + lr) * DIM_ + h * HD;
    const size_t qrow8 = qrow0 + 8 * DIM_;
    uint32_t qa_h[4][4], qa_l[4][4];
#pragma unroll
    for (int t = 0; t < 4; t++) {
        const int c0 = t * 16 + 2 * lc;
        qa_h[t][0] = *(const uint32_t*)(g_qh + qrow0 + c0);
        qa_h[t][1] = *(const uint32_t*)(g_qh + qrow8 + c0);
        qa_h[t][2] = *(const uint32_t*)(g_qh + qrow0 + c0 + 8);
        qa_h[t][3] = *(const uint32_t*)(g_qh + qrow8 + c0 + 8);
        qa_l[t][0] = *(const uint32_t*)(g_ql + qrow0 + c0);
        qa_l[t][1] = *(const uint32_t*)(g_ql + qrow8 + c0);
        qa_l[t][2] = *(const uint32_t*)(g_ql + qrow0 + c0 + 8);
        qa_l[t][3] = *(const uint32_t*)(g_ql + qrow8 + c0 + 8);
    }

    load_tiles(0, 0);

    float ofr[8][4];
#pragma unroll
    for (int j = 0; j < 8; j++)
#pragma unroll
        for (int q = 0; q < 4; q++) ofr[j][q] = 0.0f;
    float m0 = -1e30f, m1 = -1e30f, l0 = 0.0f, l1 = 0.0f;

    const int gr0 = qb * 64 + wid * 16 + lr;
    const int gr8 = gr0 + 8;

    const int l7  = lane & 7;
    const int lk8 = (lane >> 4) * 8;
    const int ld8 = ((lane >> 3) & 1) * 8;

    for (int kb = 0; kb <= qb; kb++) {
        CP_WAIT0();
        __syncthreads();
        if (kb < qb) load_tiles(kb + 1, (kb + 1) & 1);

        const uint32_t sb  = sbase + (kb & 1) * ATT_STAGE;
        const uint32_t Khs = sb;
        const uint32_t Kls = sb + 8192;
        const uint32_t Vhs = sb + 16384;
        const uint32_t Vls = sb + 24576;

        float sfr[8][4];
#pragma unroll
        for (int j = 0; j < 8; j++)
#pragma unroll
            for (int q = 0; q < 4; q++) sfr[j][q] = 0.0f;

#pragma unroll
        for (int t = 0; t < 4; t++) {
#pragma unroll
            for (int jp = 0; jp < 4; jp++) {
                const uint32_t off = SWZ128((uint32_t)((jp * 16 + lk8 + l7) * 128
                                                       + (t * 16 + ld8) * 2));
                uint32_t kh[4], kl[4];
                ldm_x4(kh, Khs + off);
                ldm_x4(kl, Kls + off);
                mma16816(sfr[2*jp],   qa_h[t][0], qa_h[t][1], qa_h[t][2], qa_h[t][3], kh[0], kh[1]);
                mma16816(sfr[2*jp],   qa_h[t][0], qa_h[t][1], qa_h[t][2], qa_h[t][3], kl[0], kl[1]);
                mma16816(sfr[2*jp],   qa_l[t][0], qa_l[t][1], qa_l[t][2], qa_l[t][3], kh[0], kh[1]);
                mma16816(sfr[2*jp+1], qa_h[t][0], qa_h[t][1], qa_h[t][2], qa_h[t][3], kh[2], kh[3]);
                mma16816(sfr[2*jp+1], qa_h[t][0], qa_h[t][1], qa_h[t][2], qa_h[t][3], kl[2], kl[3]);
                mma16816(sfr[2*jp+1], qa_l[t][0], qa_l[t][1], qa_l[t][2], qa_l[t][3], kh[2], kh[3]);
            }
        }

        const bool diag = (kb == qb);
#pragma unroll
        for (int j = 0; j < 8; j++) {
            const int gc = kb * 64 + j * 8 + 2 * lc;
            float v0 = sfr[j][0] * ATTN_SCALE;
            float v1 = sfr[j][1] * ATTN_SCALE;
            float v2 = sfr[j][2] * ATTN_SCALE;
            float v3 = sfr[j][3] * ATTN_SCALE;
            if (diag) {
                if (gc     > gr0) v0 = -1e30f;
                if (gc + 1 > gr0) v1 = -1e30f;
                if (gc     > gr8) v2 = -1e30f;
                if (gc + 1 > gr8) v3 = -1e30f;
            }
            sfr[j][0] = v0; sfr[j][1] = v1; sfr[j][2] = v2; sfr[j][3] = v3;
        }

        float mx0 = -1e30f, mx1 = -1e30f;
#pragma unroll
        for (int j = 0; j < 8; j++) {
            mx0 = fmaxf(mx0, fmaxf(sfr[j][0], sfr[j][1]));
            mx1 = fmaxf(mx1, fmaxf(sfr[j][2], sfr[j][3]));
        }
        mx0 = fmaxf(mx0, __shfl_xor_sync(0xffffffffu, mx0, 1));
        mx0 = fmaxf(mx0, __shfl_xor_sync(0xffffffffu, mx0, 2));
        mx1 = fmaxf(mx1, __shfl_xor_sync(0xffffffffu, mx1, 1));
        mx1 = fmaxf(mx1, __shfl_xor_sync(0xffffffffu, mx1, 2));
        const float mn0 = fmaxf(m0, mx0);
        const float mn1 = fmaxf(m1, mx1);
        const float cor0 = __expf(m0 - mn0);
        const float cor1 = __expf(m1 - mn1);
        m0 = mn0; m1 = mn1;
        float s0 = 0.0f, s1 = 0.0f;
#pragma unroll
        for (int j = 0; j < 8; j++) {
            sfr[j][0] = __expf(sfr[j][0] - mn0);
            sfr[j][1] = __expf(sfr[j][1] - mn0);
            sfr[j][2] = __expf(sfr[j][2] - mn1);
            sfr[j][3] = __expf(sfr[j][3] - mn1);
            s0 += sfr[j][0] + sfr[j][1];
            s1 += sfr[j][2] + sfr[j][3];
        }
        s0 += __shfl_xor_sync(0xffffffffu, s0, 1);
        s0 += __shfl_xor_sync(0xffffffffu, s0, 2);
        s1 += __shfl_xor_sync(0xffffffffu, s1, 1);
        s1 += __shfl_xor_sync(0xffffffffu, s1, 2);
        l0 = l0 * cor0 + s0;
        l1 = l1 * cor1 + s1;

#pragma unroll
        for (int j = 0; j < 8; j++) {
            ofr[j][0] *= cor0; ofr[j][1] *= cor0;
            ofr[j][2] *= cor1; ofr[j][3] *= cor1;
        }

#pragma unroll
        for (int u = 0; u < 4; u++) {
            __nv_bfloat16 b00 = __float2bfloat16(sfr[2*u][0]);
            __nv_bfloat16 b01 = __float2bfloat16(sfr[2*u][1]);
            __nv_bfloat16 b02 = __float2bfloat16(sfr[2*u][2]);
            __nv_bfloat16 b03 = __float2bfloat16(sfr[2*u][3]);
            __nv_bfloat16 b10 = __float2bfloat16(sfr[2*u+1][0]);
            __nv_bfloat16 b11 = __float2bfloat16(sfr[2*u+1][1]);
            __nv_bfloat16 b12 = __float2bfloat16(sfr[2*u+1][2]);
            __nv_bfloat16 b13 = __float2bfloat16(sfr[2*u+1][3]);
            uint32_t pah0 = pack_bf16(b00, b01);
            uint32_t pah1 = pack_bf16(b02, b03);
            uint32_t pah2 = pack_bf16(b10, b11);
            uint32_t pah3 = pack_bf16(b12, b13);
            uint32_t pal0 = pack_bf16(__float2bfloat16(sfr[2*u][0]   - __bfloat162float(b00)),
                                      __float2bfloat16(sfr[2*u][1]   - __bfloat162float(b01)));
            uint32_t pal1 = pack_bf16(__float2bfloat16(sfr[2*u][2]   - __bfloat162float(b02)),
                                      __float2bfloat16(sfr[2*u][3]   - __bfloat162float(b03)));
            uint32_t pal2 = pack_bf16(__float2bfloat16(sfr[2*u+1][0] - __bfloat162float(b10)),
                                      __float2bfloat16(sfr[2*u+1][1] - __bfloat162float(b11)));
            uint32_t pal3 = pack_bf16(__float2bfloat16(sfr[2*u+1][2] - __bfloat162float(b12)),
                                      __float2bfloat16(sfr[2*u+1][3] - __bfloat162float(b13)));
#pragma unroll
            for (int jp = 0; jp < 4; jp++) {
                const uint32_t off = SWZ128((uint32_t)((u * 16 + ld8 + l7) * 128
                                                       + (jp * 16 + lk8) * 2));
                uint32_t vh[4], vl[4];
                ldm_x4_t(vh, Vhs + off);
                ldm_x4_t(vl, Vls + off);
                mma16816(ofr[2*jp],   pah0, pah1, pah2, pah3, vh[0], vh[1]);
                mma16816(ofr[2*jp],   pah0, pah1, pah2, pah3, vl[0], vl[1]);
                mma16816(ofr[2*jp],   pal0, pal1, pal2, pal3, vh[0], vh[1]);
                mma16816(ofr[2*jp+1], pah0, pah1, pah2, pah3, vh[2], vh[3]);
                mma16816(ofr[2*jp+1], pah0, pah1, pah2, pah3, vl[2], vl[3]);
                mma16816(ofr[2*jp+1], pal0, pal1, pal2, pal3, vh[2], vh[3]);
            }
        }
    }

    const float inv0 = 1.0f / l0;
    const float inv1 = 1.0f / l1;
    __nv_bfloat16* Y0 = g_ybig + (size_t)gr0 * 2048 + h * HD;
    __nv_bfloat16* Y8 = g_ybig + (size_t)gr8 * 2048 + h * HD;
#pragma unroll
    for (int j2 = 0; j2 < 8; j2++) {
        const int cc = j2 * 8 + 2 * lc;
        float y0 = ofr[j2][0] * inv0, y1 = ofr[j2][1] * inv0;
        float y2 = ofr[j2][2] * inv1, y3 = ofr[j2][3] * inv1;
        __nv_bfloat16 h0 = __float2bfloat16(y0), h1 = __float2bfloat16(y1);
        __nv_bfloat16 h2 = __float2bfloat16(y2), h3 = __float2bfloat16(y3);
        *(uint32_t*)(Y0 + cc)        = pack_bf16(h0, h1);
        *(uint32_t*)(Y8 + cc)        = pack_bf16(h2, h3);
        *(uint32_t*)(Y0 + 1024 + cc) = pack_bf16(__float2bfloat16(y0 - __bfloat162float(h0)),
                                                 __float2bfloat16(y1 - __bfloat162float(h1)));
        *(uint32_t*)(Y8 + 1024 + cc) = pack_bf16(__float2bfloat16(y2 - __bfloat162float(h2)),
                                                 __float2bfloat16(y3 - __bfloat162float(h3)));
    }
}

// ---------------- launcher ------------------------------------------------------
extern "C" void kernel_launch(void* const* d_in, const int* in_sizes, int n_in,
                              void* d_out, int out_size)
{
    const float* x    = (const float*)d_in[0];
    const float* Wq   = (const float*)d_in[1];
    const float* Wk   = (const float*)d_in[2];
    const float* Wv   = (const float*)d_in[3];
    const float* Wo   = (const float*)d_in[4];
    const float* s_qk = (const float*)d_in[5];
    float* out = (float*)d_out;

    cudaFuncSetAttribute(gemm_mma, cudaFuncAttributeMaxDynamicSharedMemorySize,
                         GEMM_SMEM);
    cudaFuncSetAttribute(attn_mma, cudaFuncAttributeMaxDynamicSharedMemorySize,
                         ATT_SMEM);

    // operand prep
    split_kernel<<<2048, 256>>>(x);
    wconv_kernel<<<dim3(32, 32, 4), 256>>>(Wq, Wk, Wv, Wo);

    // QKV projections (split-bf16, logical K'=3072) — 64x64 warp tile, no spills
    gemm_mma<<<dim3(8, 16, 3), 128, GEMM_SMEM>>>(0, nullptr);

    // norm + rope + bf16 split for attention
    normrope_kernel<<<T_LEN, 512>>>(s_qk);

    // pipelined flash attention (epilogue feeds g_ybig directly)
    attn_mma<<<dim3(32, NHEAD), 128, ATT_SMEM>>>();

    // output projection
    gemm_mma<<<dim3(8, 16, 1), 128, GEMM_SMEM>>>(1, out);
}

// round 14
// speedup vs baseline: 1.1176x; 1.0024x over previous
#include <cuda_runtime.h>
#include <cuda_bf16.h>
#include <math.h>
#include <stdint.h>

#define T_LEN 2048
#define DIM_  1024
#define NHEAD 16
#define HD    64
#define ATTN_SCALE 0.12f

// ---------------- scratch (static device memory; no allocations) ----------------
__device__ float g_q[T_LEN * DIM_];
__device__ float g_k[T_LEN * DIM_];
__device__ float g_v[T_LEN * DIM_];
// split-bf16 operands for GEMMs: [.,0:1024)=hi, [.,1024:2048)=lo
__device__ __nv_bfloat16 g_abig[T_LEN * 2048];
__device__ __nv_bfloat16 g_ybig[T_LEN * 2048];
__device__ __nv_bfloat16 g_wt[4][1024 * 2048];
// split-bf16 q/k/v for attention (post norm+rope), layout [t][1024]
__device__ __nv_bfloat16 g_qh[T_LEN * DIM_], g_ql[T_LEN * DIM_];
__device__ __nv_bfloat16 g_kh[T_LEN * DIM_], g_kl[T_LEN * DIM_];
__device__ __nv_bfloat16 g_vh[T_LEN * DIM_], g_vl[T_LEN * DIM_];

// rotary freqs (fp32 of 2^(-2i/3), matches (1/1024)^(i/15) computed in double)
__constant__ float FREQ16[16] = {
    1.0f, 0.6299605249474366f, 0.3968502629920499f, 0.25f,
    0.15749013123685915f, 0.09921256574801247f, 0.0625f, 0.03937253280921479f,
    0.024803141437003118f, 0.015625f, 0.009843133202303698f, 0.0062007853592507794f,
    0.00390625f, 0.0024607833005759246f, 0.0015501963398126949f, 0.0009765625f
};

// ---------------- PTX helpers ----------------------------------------------------
__device__ __forceinline__ uint32_t smem_u32(const void* p) {
    uint32_t a;
    asm("{ .reg .u64 t; cvta.to.shared.u64 t, %1; cvt.u32.u64 %0, t; }" : "=r"(a) : "l"(p));
    return a;
}
__device__ __forceinline__ void mma16816(float c[4],
                                         uint32_t a0, uint32_t a1, uint32_t a2, uint32_t a3,
                                         uint32_t b0, uint32_t b1)
{
    asm volatile("mma.sync.aligned.m16n8k16.row.col.f32.bf16.bf16.f32 "
                 "{%0,%1,%2,%3}, {%4,%5,%6,%7}, {%8,%9}, {%0,%1,%2,%3};"
                 : "+f"(c[0]), "+f"(c[1]), "+f"(c[2]), "+f"(c[3])
                 : "r"(a0), "r"(a1), "r"(a2), "r"(a3), "r"(b0), "r"(b1));
}
__device__ __forceinline__ void ldm_x4(uint32_t r[4], uint32_t addr) {
    asm volatile("ldmatrix.sync.aligned.m8n8.x4.shared.b16 {%0,%1,%2,%3}, [%4];"
                 : "=r"(r[0]), "=r"(r[1]), "=r"(r[2]), "=r"(r[3]) : "r"(addr));
}
__device__ __forceinline__ void ldm_x4_t(uint32_t r[4], uint32_t addr) {
    asm volatile("ldmatrix.sync.aligned.m8n8.x4.trans.shared.b16 {%0,%1,%2,%3}, [%4];"
                 : "=r"(r[0]), "=r"(r[1]), "=r"(r[2]), "=r"(r[3]) : "r"(addr));
}
__device__ __forceinline__ uint32_t pack_bf16(__nv_bfloat16 lo, __nv_bfloat16 hi)
{
    __nv_bfloat162 t; t.x = lo; t.y = hi;
    return *(uint32_t*)&t;
}
#define CP_ASYNC16(dst, src) \
    asm volatile("cp.async.cg.shared.global [%0], [%1], 16;" :: "r"(dst), "l"(src))
#define CP_COMMIT()  asm volatile("cp.async.commit_group;" ::: "memory")
#define CP_WAIT1()   asm volatile("cp.async.wait_group 1;" ::: "memory")
#define CP_WAIT0()   asm volatile("cp.async.wait_group 0;" ::: "memory")
#define SWZ128(o)    ((o) ^ (((o) >> 3) & 0x70))
#define SWZ64(o)     ((o) ^ (((o) >> 3) & 0x30))

// ---------------- split conversion (x -> hi|lo bf16) ----------------------------
__global__ __launch_bounds__(256) void split_kernel(const float* __restrict__ xin)
{
    int idx = blockIdx.x * 256 + threadIdx.x;
    float4 v = ((const float4*)xin)[idx];
    int m  = idx >> 8;
    int c0 = (idx & 255) << 2;
    __nv_bfloat16 h0 = __float2bfloat16(v.x), h1 = __float2bfloat16(v.y);
    __nv_bfloat16 h2 = __float2bfloat16(v.z), h3 = __float2bfloat16(v.w);
    __nv_bfloat16 l0 = __float2bfloat16(v.x - __bfloat162float(h0));
    __nv_bfloat16 l1 = __float2bfloat16(v.y - __bfloat162float(h1));
    __nv_bfloat16 l2 = __float2bfloat16(v.z - __bfloat162float(h2));
    __nv_bfloat16 l3 = __float2bfloat16(v.w - __bfloat162float(h3));
    __nv_bfloat16* po = g_abig + (size_t)m * 2048 + c0;
    po[0] = h0; po[1] = h1; po[2] = h2; po[3] = h3;
    po[1024] = l0; po[1025] = l1; po[1026] = l2; po[1027] = l3;
}

// ---------------- weight transpose + split: W[k][n] -> WT[n][k_hi | k_lo] -------
__global__ __launch_bounds__(256) void wconv_kernel(const float* __restrict__ Wq,
                                                    const float* __restrict__ Wk,
                                                    const float* __restrict__ Wv,
                                                    const float* __restrict__ Wo)
{
    __shared__ float tile[32][33];
    const int z = blockIdx.z;
    const float* W = (z == 0) ? Wq : (z == 1) ? Wk : (z == 2) ? Wv : Wo;
    __nv_bfloat16* WT = g_wt[z];
    const int tx = threadIdx.x & 31, ty = threadIdx.x >> 5;
    const int n  = blockIdx.x * 32 + tx;
    const int k0 = blockIdx.y * 32;
#pragma unroll
    for (int i = 0; i < 4; i++)
        tile[ty + i * 8][tx] = W[(size_t)(k0 + ty + i * 8) * 1024 + n];
    __syncthreads();
#pragma unroll
    for (int i = 0; i < 4; i++) {
        float v = tile[tx][ty + i * 8];
        __nv_bfloat16 hi = __float2bfloat16(v);
        __nv_bfloat16 lo = __float2bfloat16(v - __bfloat162float(hi));
        size_t base = (size_t)(blockIdx.x * 32 + ty + i * 8) * 2048 + k0 + tx;
        WT[base]        = hi;
        WT[base + 1024] = lo;
    }
}

// ---------------- operand-shared split-bf16 GEMM v4 -----------------------------
// CTA 128x128, 256 thr, 8 warps (4m x 2n), warp tile 32x64. 32 chunks of K=32;
// each chunk loads Ah|Al|Bh|Bl ONCE (8KB each, 32KB stage) and computes the
// three split terms from smem -> per-CTA traffic 1.5MB -> 1.0MB. 3-stage
// cp.async (96KB smem, 2 CTA/SM), 64B rows with SWZ64 swizzle.
#define GEMM_NCHUNK 32
#define GSTAGES 3
#define STAGE_BYTES 32768
#define GEMM_SMEM (GSTAGES * STAGE_BYTES)

__global__ __launch_bounds__(256, 2) void gemm_mma(int proj, float* __restrict__ outp)
{
    extern __shared__ char smg[];
    const uint32_t sbase = smem_u32(smg);
    const int tid  = threadIdx.x;
    const int wid  = tid >> 5;
    const int lane = tid & 31;
    const int n0 = blockIdx.x * 128;
    const int m0 = blockIdx.y * 128;
    const int z  = blockIdx.z;

    const __nv_bfloat16* A  = proj ? g_ybig : g_abig;
    const __nv_bfloat16* Bt = proj ? g_wt[3] : g_wt[z];
    float* C = proj ? outp : (z == 0 ? g_q : z == 1 ? g_k : g_v);

    const __nv_bfloat16* Ag = A  + (size_t)m0 * 2048;
    const __nv_bfloat16* Bg = Bt + (size_t)n0 * 2048;

    const int wm = wid >> 1;          // 0..3 -> m offset wm*32
    const int wn = wid & 1;           // 0..1 -> n offset wn*64
    const int quad = lane >> 3;
    const int r8   = lane & 7;

    float acc[2][8][4];
#pragma unroll
    for (int i = 0; i < 2; i++)
#pragma unroll
        for (int f = 0; f < 8; f++)
#pragma unroll
            for (int q = 0; q < 4; q++) acc[i][f][q] = 0.0f;

    // chunk loader: Ah|Al|Bh|Bl, each 128 rows x 32 bf16 (64B rows, SWZ64).
    // 2048 granules of 16B; 8 per thread.
    auto load_chunk = [&](int cn) {
        const int kc = cn * 32;
        const uint32_t st = sbase + (cn % GSTAGES) * STAGE_BYTES;
#pragma unroll
        for (int s = 0; s < 8; s++) {
            const int idx = tid + s * 256;
            const int sub = idx >> 9;            // 0:Ah 1:Al 2:Bh 3:Bl
            const int w   = idx & 511;
            const int row = w >> 2, g = w & 3;
            const uint32_t dst = st + sub * 8192 + SWZ64((uint32_t)(row * 64 + g * 16));
            const __nv_bfloat16* src =
                ((sub & 2) ? Bg : Ag) + (size_t)row * 2048 + ((sub & 1) ? 1024 : 0) + kc + g * 8;
            CP_ASYNC16(dst, (const void*)src);
        }
        CP_COMMIT();
    };

    load_chunk(0);
    load_chunk(1);

    for (int c = 0; c < GEMM_NCHUNK; c++) {
        if (c == GEMM_NCHUNK - 1) CP_WAIT0(); else CP_WAIT1();
        __syncthreads();                       // chunk c visible; stage (c-1)%3 free
        if (c + 2 < GEMM_NCHUNK) load_chunk(c + 2);

        const uint32_t st  = sbase + (c % GSTAGES) * STAGE_BYTES;
        const uint32_t Ahs = st;
        const uint32_t Als = st + 8192;
        const uint32_t Bhs = st + 16384;
        const uint32_t Bls = st + 24576;
#pragma unroll
        for (int ks = 0; ks < 2; ks++) {
            uint32_t ah[2][4], al[2][4];
            const int acb = ks * 32 + (quad >> 1) * 16;   // A col byte
            const int bcb = ks * 32 + (quad & 1) * 16;    // B col byte
#pragma unroll
            for (int i = 0; i < 2; i++) {
                const int row = wm * 32 + i * 16 + r8 + (quad & 1) * 8;
                const uint32_t off = SWZ64((uint32_t)(row * 64 + acb));
                ldm_x4(ah[i], Ahs + off);
                ldm_x4(al[i], Als + off);
            }
#pragma unroll
            for (int j = 0; j < 4; j++) {
                uint32_t bh[4], bl[4];
                const int row = wn * 64 + j * 16 + r8 + (quad >> 1) * 8;
                const uint32_t off = SWZ64((uint32_t)(row * 64 + bcb));
                ldm_x4(bh, Bhs + off);
                ldm_x4(bl, Bls + off);
#pragma unroll
                for (int i = 0; i < 2; i++) {
                    mma16816(acc[i][2*j],   ah[i][0], ah[i][1], ah[i][2], ah[i][3], bh[0], bh[1]);
                    mma16816(acc[i][2*j],   ah[i][0], ah[i][1], ah[i][2], ah[i][3], bl[0], bl[1]);
                    mma16816(acc[i][2*j],   al[i][0], al[i][1], al[i][2], al[i][3], bh[0], bh[1]);
                    mma16816(acc[i][2*j+1], ah[i][0], ah[i][1], ah[i][2], ah[i][3], bh[2], bh[3]);
                    mma16816(acc[i][2*j+1], ah[i][0], ah[i][1], ah[i][2], ah[i][3], bl[2], bl[3]);
                    mma16816(acc[i][2*j+1], al[i][0], al[i][1], al[i][2], al[i][3], bh[2], bh[3]);
                }
            }
        }
    }

    // epilogue: C fragments -> global fp32
    const int erow  = lane >> 2;
    const int ecol2 = (lane & 3) * 2;
#pragma unroll
    for (int i = 0; i < 2; i++)
#pragma unroll
        for (int f = 0; f < 8; f++) {
            float* p0 = C + (size_t)(m0 + wm * 32 + i * 16 + erow) * 1024
                          + n0 + wn * 64 + f * 8 + ecol2;
            *(float2*)p0            = make_float2(acc[i][f][0], acc[i][f][1]);
            *(float2*)(p0 + 8*1024) = make_float2(acc[i][f][2], acc[i][f][3]);
        }
}

// ---------------- cosine-norm + scale + rotary + bf16 split ---------------------
__global__ __launch_bounds__(512) void normrope_kernel(const float* __restrict__ s_qk)
{
    const int t    = blockIdx.x;
    const int h    = threadIdx.x >> 5;
    const int lane = threadIdx.x & 31;

    float c, s;
    if (lane < 16) {
        float theta = (float)t * FREQ16[lane];
        sincosf(theta, &s, &c);
    } else { c = 1.0f; s = 0.0f; }

    const float sc1 = s_qk[h * HD + lane]      * 32.0f;
    const float sc2 = s_qk[h * HD + lane + 32] * 32.0f;

    const size_t base = (size_t)t * DIM_ + h * HD;

    const float* inp[2] = {g_q + base, g_k + base};
    __nv_bfloat16* oh[2] = {g_qh + base, g_kh + base};
    __nv_bfloat16* ol[2] = {g_ql + base, g_kl + base};
#pragma unroll
    for (int w = 0; w < 2; w++) {
        const float* p = inp[w];
        float v1 = p[lane];
        float v2 = p[lane + 32];
        float ss = v1 * v1 + v2 * v2;
#pragma unroll
        for (int o = 16; o > 0; o >>= 1)
            ss += __shfl_xor_sync(0xffffffffu, ss, o);
        float rn = rsqrtf(ss + 1e-12f);
        v1 *= rn * sc1;
        v2 *= rn * sc2;
        float y1 = v1 * c + v2 * s;
        float y2 = v2 * c - v1 * s;
        __nv_bfloat16 h1 = __float2bfloat16(y1);
        __nv_bfloat16 h2 = __float2bfloat16(y2);
        oh[w][lane]      = h1;
        oh[w][lane + 32] = h2;
        ol[w][lane]      = __float2bfloat16(y1 - __bfloat162float(h1));
        ol[w][lane + 32] = __float2bfloat16(y2 - __bfloat162float(h2));
    }
    {
        float v1 = g_v[base + lane];
        float v2 = g_v[base + lane + 32];
        __nv_bfloat16 h1 = __float2bfloat16(v1);
        __nv_bfloat16 h2 = __float2bfloat16(v2);
        g_vh[base + lane]      = h1;
        g_vh[base + lane + 32] = h2;
        g_vl[base + lane]      = __float2bfloat16(v1 - __bfloat162float(h1));
        g_vl[base + lane + 32] = __float2bfloat16(v2 - __bfloat162float(h2));
    }
}

// ---------------- pipelined flash attention (R11, passing) ----------------------
#define ATT_STAGE 32768
#define ATT_SMEM  (2 * ATT_STAGE)

__global__ __launch_bounds__(128) void attn_mma()
{
    extern __shared__ char sma[];
    const uint32_t sbase = smem_u32(sma);

    const int qb   = 31 - (int)blockIdx.x;
    const int h    = blockIdx.y;
    const int tid  = threadIdx.x;
    const int wid  = tid >> 5;
    const int lane = tid & 31;
    const int lr   = lane >> 2;
    const int lc   = lane & 3;

    const __nv_bfloat16* GKh0 = g_kh + h * HD;
    const __nv_bfloat16* GKl0 = g_kl + h * HD;
    const __nv_bfloat16* GVh0 = g_vh + h * HD;
    const __nv_bfloat16* GVl0 = g_vl + h * HD;

    auto load_tiles = [&](int kb, int stage) {
        const uint32_t sb = sbase + stage * ATT_STAGE;
        const size_t gbase = (size_t)(kb * 64) * DIM_;
#pragma unroll
        for (int i = 0; i < 4; i++) {
            const int idx = tid + i * 128;
            const int row = idx >> 3, g = idx & 7;
            const uint32_t off = SWZ128((uint32_t)(row * 128 + g * 16));
            const size_t goff = gbase + (size_t)row * DIM_ + g * 8;
            CP_ASYNC16(sb + off,          (const void*)(GKh0 + goff));
            CP_ASYNC16(sb + 8192 + off,   (const void*)(GKl0 + goff));
            CP_ASYNC16(sb + 16384 + off,  (const void*)(GVh0 + goff));
            CP_ASYNC16(sb + 24576 + off,  (const void*)(GVl0 + goff));
        }
        CP_COMMIT();
    };

    const size_t qrow0 = (size_t)(qb * 64 + wid * 16 + lr) * DIM_ + h * HD;
    const size_t qrow8 = qrow0 + 8 * DIM_;
    uint32_t qa_h[4][4], qa_l[4][4];
#pragma unroll
    for (int t = 0; t < 4; t++) {
        const int c0 = t * 16 + 2 * lc;
        qa_h[t][0] = *(const uint32_t*)(g_qh + qrow0 + c0);
        qa_h[t][1] = *(const uint32_t*)(g_qh + qrow8 + c0);
        qa_h[t][2] = *(const uint32_t*)(g_qh + qrow0 + c0 + 8);
        qa_h[t][3] = *(const uint32_t*)(g_qh + qrow8 + c0 + 8);
        qa_l[t][0] = *(const uint32_t*)(g_ql + qrow0 + c0);
        qa_l[t][1] = *(const uint32_t*)(g_ql + qrow8 + c0);
        qa_l[t][2] = *(const uint32_t*)(g_ql + qrow0 + c0 + 8);
        qa_l[t][3] = *(const uint32_t*)(g_ql + qrow8 + c0 + 8);
    }

    load_tiles(0, 0);

    float ofr[8][4];
#pragma unroll
    for (int j = 0; j < 8; j++)
#pragma unroll
        for (int q = 0; q < 4; q++) ofr[j][q] = 0.0f;
    float m0 = -1e30f, m1 = -1e30f, l0 = 0.0f, l1 = 0.0f;

    const int gr0 = qb * 64 + wid * 16 + lr;
    const int gr8 = gr0 + 8;

    const int l7  = lane & 7;
    const int lk8 = (lane >> 4) * 8;
    const int ld8 = ((lane >> 3) & 1) * 8;

    for (int kb = 0; kb <= qb; kb++) {
        CP_WAIT0();
        __syncthreads();
        if (kb < qb) load_tiles(kb + 1, (kb + 1) & 1);

        const uint32_t sb  = sbase + (kb & 1) * ATT_STAGE;
        const uint32_t Khs = sb;
        const uint32_t Kls = sb + 8192;
        const uint32_t Vhs = sb + 16384;
        const uint32_t Vls = sb + 24576;

        float sfr[8][4];
#pragma unroll
        for (int j = 0; j < 8; j++)
#pragma unroll
            for (int q = 0; q < 4; q++) sfr[j][q] = 0.0f;

#pragma unroll
        for (int t = 0; t < 4; t++) {
#pragma unroll
            for (int jp = 0; jp < 4; jp++) {
                const uint32_t off = SWZ128((uint32_t)((jp * 16 + lk8 + l7) * 128
                                                       + (t * 16 + ld8) * 2));
                uint32_t kh[4], kl[4];
                ldm_x4(kh, Khs + off);
                ldm_x4(kl, Kls + off);
                mma16816(sfr[2*jp],   qa_h[t][0], qa_h[t][1], qa_h[t][2], qa_h[t][3], kh[0], kh[1]);
                mma16816(sfr[2*jp],   qa_h[t][0], qa_h[t][1], qa_h[t][2], qa_h[t][3], kl[0], kl[1]);
                mma16816(sfr[2*jp],   qa_l[t][0], qa_l[t][1], qa_l[t][2], qa_l[t][3], kh[0], kh[1]);
                mma16816(sfr[2*jp+1], qa_h[t][0], qa_h[t][1], qa_h[t][2], qa_h[t][3], kh[2], kh[3]);
                mma16816(sfr[2*jp+1], qa_h[t][0], qa_h[t][1], qa_h[t][2], qa_h[t][3], kl[2], kl[3]);
                mma16816(sfr[2*jp+1], qa_l[t][0], qa_l[t][1], qa_l[t][2], qa_l[t][3], kh[2], kh[3]);
            }
        }

        const bool diag = (kb == qb);
#pragma unroll
        for (int j = 0; j < 8; j++) {
            const int gc = kb * 64 + j * 8 + 2 * lc;
            float v0 = sfr[j][0] * ATTN_SCALE;
            float v1 = sfr[j][1] * ATTN_SCALE;
            float v2 = sfr[j][2] * ATTN_SCALE;
            float v3 = sfr[j][3] * ATTN_SCALE;
            if (diag) {
                if (gc     > gr0) v0 = -1e30f;
                if (gc + 1 > gr0) v1 = -1e30f;
                if (gc     > gr8) v2 = -1e30f;
                if (gc + 1 > gr8) v3 = -1e30f;
            }
            sfr[j][0] = v0; sfr[j][1] = v1; sfr[j][2] = v2; sfr[j][3] = v3;
        }

        float mx0 = -1e30f, mx1 = -1e30f;
#pragma unroll
        for (int j = 0; j < 8; j++) {
            mx0 = fmaxf(mx0, fmaxf(sfr[j][0], sfr[j][1]));
            mx1 = fmaxf(mx1, fmaxf(sfr[j][2], sfr[j][3]));
        }
        mx0 = fmaxf(mx0, __shfl_xor_sync(0xffffffffu, mx0, 1));
        mx0 = fmaxf(mx0, __shfl_xor_sync(0xffffffffu, mx0, 2));
        mx1 = fmaxf(mx1, __shfl_xor_sync(0xffffffffu, mx1, 1));
        mx1 = fmaxf(mx1, __shfl_xor_sync(0xffffffffu, mx1, 2));
        const float mn0 = fmaxf(m0, mx0);
        const float mn1 = fmaxf(m1, mx1);
        const float cor0 = __expf(m0 - mn0);
        const float cor1 = __expf(m1 - mn1);
        m0 = mn0; m1 = mn1;
        float s0 = 0.0f, s1 = 0.0f;
#pragma unroll
        for (int j = 0; j < 8; j++) {
            sfr[j][0] = __expf(sfr[j][0] - mn0);
            sfr[j][1] = __expf(sfr[j][1] - mn0);
            sfr[j][2] = __expf(sfr[j][2] - mn1);
            sfr[j][3] = __expf(sfr[j][3] - mn1);
            s0 += sfr[j][0] + sfr[j][1];
            s1 += sfr[j][2] + sfr[j][3];
        }
        s0 += __shfl_xor_sync(0xffffffffu, s0, 1);
        s0 += __shfl_xor_sync(0xffffffffu, s0, 2);
        s1 += __shfl_xor_sync(0xffffffffu, s1, 1);
        s1 += __shfl_xor_sync(0xffffffffu, s1, 2);
        l0 = l0 * cor0 + s0;
        l1 = l1 * cor1 + s1;

#pragma unroll
        for (int j = 0; j < 8; j++) {
            ofr[j][0] *= cor0; ofr[j][1] *= cor0;
            ofr[j][2] *= cor1; ofr[j][3] *= cor1;
        }

#pragma unroll
        for (int u = 0; u < 4; u++) {
            __nv_bfloat16 b00 = __float2bfloat16(sfr[2*u][0]);
            __nv_bfloat16 b01 = __float2bfloat16(sfr[2*u][1]);
            __nv_bfloat16 b02 = __float2bfloat16(sfr[2*u][2]);
            __nv_bfloat16 b03 = __float2bfloat16(sfr[2*u][3]);
            __nv_bfloat16 b10 = __float2bfloat16(sfr[2*u+1][0]);
            __nv_bfloat16 b11 = __float2bfloat16(sfr[2*u+1][1]);
            __nv_bfloat16 b12 = __float2bfloat16(sfr[2*u+1][2]);
            __nv_bfloat16 b13 = __float2bfloat16(sfr[2*u+1][3]);
            uint32_t pah0 = pack_bf16(b00, b01);
            uint32_t pah1 = pack_bf16(b02, b03);
            uint32_t pah2 = pack_bf16(b10, b11);
            uint32_t pah3 = pack_bf16(b12, b13);
            uint32_t pal0 = pack_bf16(__float2bfloat16(sfr[2*u][0]   - __bfloat162float(b00)),
                                      __float2bfloat16(sfr[2*u][1]   - __bfloat162float(b01)));
            uint32_t pal1 = pack_bf16(__float2bfloat16(sfr[2*u][2]   - __bfloat162float(b02)),
                                      __float2bfloat16(sfr[2*u][3]   - __bfloat162float(b03)));
            uint32_t pal2 = pack_bf16(__float2bfloat16(sfr[2*u+1][0] - __bfloat162float(b10)),
                                      __float2bfloat16(sfr[2*u+1][1] - __bfloat162float(b11)));
            uint32_t pal3 = pack_bf16(__float2bfloat16(sfr[2*u+1][2] - __bfloat162float(b12)),
                                      __float2bfloat16(sfr[2*u+1][3] - __bfloat162float(b13)));
#pragma unroll
            for (int jp = 0; jp < 4; jp++) {
                const uint32_t off = SWZ128((uint32_t)((u * 16 + ld8 + l7) * 128
                                                       + (jp * 16 + lk8) * 2));
                uint32_t vh[4], vl[4];
                ldm_x4_t(vh, Vhs + off);
                ldm_x4_t(vl, Vls + off);
                mma16816(ofr[2*jp],   pah0, pah1, pah2, pah3, vh[0], vh[1]);
                mma16816(ofr[2*jp],   pah0, pah1, pah2, pah3, vl[0], vl[1]);
                mma16816(ofr[2*jp],   pal0, pal1, pal2, pal3, vh[0], vh[1]);
                mma16816(ofr[2*jp+1], pah0, pah1, pah2, pah3, vh[2], vh[3]);
                mma16816(ofr[2*jp+1], pah0, pah1, pah2, pah3, vl[2], vl[3]);
                mma16816(ofr[2*jp+1], pal0, pal1, pal2, pal3, vh[2], vh[3]);
            }
        }
    }

    const float inv0 = 1.0f / l0;
    const float inv1 = 1.0f / l1;
    __nv_bfloat16* Y0 = g_ybig + (size_t)gr0 * 2048 + h * HD;
    __nv_bfloat16* Y8 = g_ybig + (size_t)gr8 * 2048 + h * HD;
#pragma unroll
    for (int j2 = 0; j2 < 8; j2++) {
        const int cc = j2 * 8 + 2 * lc;
        float y0 = ofr[j2][0] * inv0, y1 = ofr[j2][1] * inv0;
        float y2 = ofr[j2][2] * inv1, y3 = ofr[j2][3] * inv1;
        __nv_bfloat16 h0 = __float2bfloat16(y0), h1 = __float2bfloat16(y1);
        __nv_bfloat16 h2 = __float2bfloat16(y2), h3 = __float2bfloat16(y3);
        *(uint32_t*)(Y0 + cc)        = pack_bf16(h0, h1);
        *(uint32_t*)(Y8 + cc)        = pack_bf16(h2, h3);
        *(uint32_t*)(Y0 + 1024 + cc) = pack_bf16(__float2bfloat16(y0 - __bfloat162float(h0)),
                                                 __float2bfloat16(y1 - __bfloat162float(h1)));
        *(uint32_t*)(Y8 + 1024 + cc) = pack_bf16(__float2bfloat16(y2 - __bfloat162float(h2)),
                                                 __float2bfloat16(y3 - __bfloat162float(h3)));
    }
}

// ---------------- launcher ------------------------------------------------------
extern "C" void kernel_launch(void* const* d_in, const int* in_sizes, int n_in,
                              void* d_out, int out_size)
{
    const float* x    = (const float*)d_in[0];
    const float* Wq   = (const float*)d_in[1];
    const float* Wk   = (const float*)d_in[2];
    const float* Wv   = (const float*)d_in[3];
    const float* Wo   = (const float*)d_in[4];
    const float* s_qk = (const float*)d_in[5];
    float* out = (float*)d_out;

    cudaFuncSetAttribute(gemm_mma, cudaFuncAttributeMaxDynamicSharedMemorySize,
                         GEMM_SMEM);
    cudaFuncSetAttribute(attn_mma, cudaFuncAttributeMaxDynamicSharedMemorySize,
                         ATT_SMEM);

    // operand prep
    split_kernel<<<2048, 256>>>(x);
    wconv_kernel<<<dim3(32, 32, 4), 256>>>(Wq, Wk, Wv, Wo);

    // QKV projections (split-bf16, operand-shared chunks, 33% less traffic)
    gemm_mma<<<dim3(8, 16, 3), 256, GEMM_SMEM>>>(0, nullptr);

    // norm + rope + bf16 split for attention
    normrope_kernel<<<T_LEN, 512>>>(s_qk);

    // pipelined flash attention (epilogue feeds g_ybig directly)
    attn_mma<<<dim3(32, NHEAD), 128, ATT_SMEM>>>();

    // output projection
    gemm_mma<<<dim3(8, 16, 1), 256, GEMM_SMEM>>>(1, out);
}

// round 15
// speedup vs baseline: 1.2340x; 1.1041x over previous
#include <cuda_runtime.h>
#include <cuda_bf16.h>
#include <math.h>
#include <stdint.h>

#define T_LEN 2048
#define DIM_  1024
#define NHEAD 16
#define HD    64
#define ATTN_SCALE 0.12f

// ---------------- scratch (static device memory; no allocations) ----------------
// split-bf16 operands for GEMMs: [.,0:1024)=hi, [.,1024:2048)=lo
__device__ __nv_bfloat16 g_abig[T_LEN * 2048];
__device__ __nv_bfloat16 g_ybig[T_LEN * 2048];
__device__ __nv_bfloat16 g_wt[4][1024 * 2048];
// split-bf16 q/k/v for attention (post norm+rope), layout [t][1024]
__device__ __nv_bfloat16 g_qh[T_LEN * DIM_], g_ql[T_LEN * DIM_];
__device__ __nv_bfloat16 g_kh[T_LEN * DIM_], g_kl[T_LEN * DIM_];
__device__ __nv_bfloat16 g_vh[T_LEN * DIM_], g_vl[T_LEN * DIM_];

// rotary freqs (fp32 of 2^(-2i/3), matches (1/1024)^(i/15) computed in double)
__constant__ float FREQ16[16] = {
    1.0f, 0.6299605249474366f, 0.3968502629920499f, 0.25f,
    0.15749013123685915f, 0.09921256574801247f, 0.0625f, 0.03937253280921479f,
    0.024803141437003118f, 0.015625f, 0.009843133202303698f, 0.0062007853592507794f,
    0.00390625f, 0.0024607833005759246f, 0.0015501963398126949f, 0.0009765625f
};

// ---------------- PTX helpers ----------------------------------------------------
__device__ __forceinline__ uint32_t smem_u32(const void* p) {
    uint32_t a;
    asm("{ .reg .u64 t; cvta.to.shared.u64 t, %1; cvt.u32.u64 %0, t; }" : "=r"(a) : "l"(p));
    return a;
}
__device__ __forceinline__ void mma16816(float c[4],
                                         uint32_t a0, uint32_t a1, uint32_t a2, uint32_t a3,
                                         uint32_t b0, uint32_t b1)
{
    asm volatile("mma.sync.aligned.m16n8k16.row.col.f32.bf16.bf16.f32 "
                 "{%0,%1,%2,%3}, {%4,%5,%6,%7}, {%8,%9}, {%0,%1,%2,%3};"
                 : "+f"(c[0]), "+f"(c[1]), "+f"(c[2]), "+f"(c[3])
                 : "r"(a0), "r"(a1), "r"(a2), "r"(a3), "r"(b0), "r"(b1));
}
__device__ __forceinline__ void ldm_x4(uint32_t r[4], uint32_t addr) {
    asm volatile("ldmatrix.sync.aligned.m8n8.x4.shared.b16 {%0,%1,%2,%3}, [%4];"
                 : "=r"(r[0]), "=r"(r[1]), "=r"(r[2]), "=r"(r[3]) : "r"(addr));
}
__device__ __forceinline__ void ldm_x4_t(uint32_t r[4], uint32_t addr) {
    asm volatile("ldmatrix.sync.aligned.m8n8.x4.trans.shared.b16 {%0,%1,%2,%3}, [%4];"
                 : "=r"(r[0]), "=r"(r[1]), "=r"(r[2]), "=r"(r[3]) : "r"(addr));
}
__device__ __forceinline__ uint32_t pack_bf16(__nv_bfloat16 lo, __nv_bfloat16 hi)
{
    __nv_bfloat162 t; t.x = lo; t.y = hi;
    return *(uint32_t*)&t;
}
#define CP_ASYNC16(dst, src) \
    asm volatile("cp.async.cg.shared.global [%0], [%1], 16;" :: "r"(dst), "l"(src))
#define CP_COMMIT()  asm volatile("cp.async.commit_group;" ::: "memory")
#define CP_WAIT1()   asm volatile("cp.async.wait_group 1;" ::: "memory")
#define CP_WAIT0()   asm volatile("cp.async.wait_group 0;" ::: "memory")
#define SWZ128(o)    ((o) ^ (((o) >> 3) & 0x70))
#define SWZ64(o)     ((o) ^ (((o) >> 3) & 0x30))

// ---------------- split conversion (x -> hi|lo bf16) ----------------------------
__global__ __launch_bounds__(256) void split_kernel(const float* __restrict__ xin)
{
    int idx = blockIdx.x * 256 + threadIdx.x;
    float4 v = ((const float4*)xin)[idx];
    int m  = idx >> 8;
    int c0 = (idx & 255) << 2;
    __nv_bfloat16 h0 = __float2bfloat16(v.x), h1 = __float2bfloat16(v.y);
    __nv_bfloat16 h2 = __float2bfloat16(v.z), h3 = __float2bfloat16(v.w);
    __nv_bfloat16 l0 = __float2bfloat16(v.x - __bfloat162float(h0));
    __nv_bfloat16 l1 = __float2bfloat16(v.y - __bfloat162float(h1));
    __nv_bfloat16 l2 = __float2bfloat16(v.z - __bfloat162float(h2));
    __nv_bfloat16 l3 = __float2bfloat16(v.w - __bfloat162float(h3));
    __nv_bfloat16* po = g_abig + (size_t)m * 2048 + c0;
    po[0] = h0; po[1] = h1; po[2] = h2; po[3] = h3;
    po[1024] = l0; po[1025] = l1; po[1026] = l2; po[1027] = l3;
}

// ---------------- weight transpose + split: W[k][n] -> WT[n][k_hi | k_lo] -------
__global__ __launch_bounds__(256) void wconv_kernel(const float* __restrict__ Wq,
                                                    const float* __restrict__ Wk,
                                                    const float* __restrict__ Wv,
                                                    const float* __restrict__ Wo)
{
    __shared__ float tile[32][33];
    const int z = blockIdx.z;
    const float* W = (z == 0) ? Wq : (z == 1) ? Wk : (z == 2) ? Wv : Wo;
    __nv_bfloat16* WT = g_wt[z];
    const int tx = threadIdx.x & 31, ty = threadIdx.x >> 5;
    const int n  = blockIdx.x * 32 + tx;
    const int k0 = blockIdx.y * 32;
#pragma unroll
    for (int i = 0; i < 4; i++)
        tile[ty + i * 8][tx] = W[(size_t)(k0 + ty + i * 8) * 1024 + n];
    __syncthreads();
#pragma unroll
    for (int i = 0; i < 4; i++) {
        float v = tile[tx][ty + i * 8];
        __nv_bfloat16 hi = __float2bfloat16(v);
        __nv_bfloat16 lo = __float2bfloat16(v - __bfloat162float(hi));
        size_t base = (size_t)(blockIdx.x * 32 + ty + i * 8) * 2048 + k0 + tx;
        WT[base]        = hi;
        WT[base + 1024] = lo;
    }
}

// ---------------- operand-shared split-bf16 GEMM + fused norm/rope epilogue -----
// Mainloop = R14 (passing). Epilogue: proj -> fp32 out; z<2 -> cosine-norm +
// s_eff scale + rotary + bf16 hi/lo split into g_{q,k}{h,l}; z==2 -> split to
// g_v{h,l}. Warp tile 32x64 holds complete head rows -> warp-local norm.
#define GEMM_NCHUNK 32
#define GSTAGES 3
#define STAGE_BYTES 32768
#define GEMM_SMEM (GSTAGES * STAGE_BYTES)

__global__ __launch_bounds__(256, 2) void gemm_mma(int proj, float* __restrict__ outp,
                                                   const float* __restrict__ s_qk)
{
    extern __shared__ char smg[];
    const uint32_t sbase = smem_u32(smg);
    const int tid  = threadIdx.x;
    const int wid  = tid >> 5;
    const int lane = tid & 31;
    const int n0 = blockIdx.x * 128;
    const int m0 = blockIdx.y * 128;
    const int z  = blockIdx.z;

    const __nv_bfloat16* A  = proj ? g_ybig : g_abig;
    const __nv_bfloat16* Bt = proj ? g_wt[3] : g_wt[z];

    const __nv_bfloat16* Ag = A  + (size_t)m0 * 2048;
    const __nv_bfloat16* Bg = Bt + (size_t)n0 * 2048;

    const int wm = wid >> 1;          // 0..3 -> m offset wm*32
    const int wn = wid & 1;           // 0..1 -> n offset wn*64
    const int quad = lane >> 3;
    const int r8   = lane & 7;

    float acc[2][8][4];
#pragma unroll
    for (int i = 0; i < 2; i++)
#pragma unroll
        for (int f = 0; f < 8; f++)
#pragma unroll
            for (int q = 0; q < 4; q++) acc[i][f][q] = 0.0f;

    auto load_chunk = [&](int cn) {
        const int kc = cn * 32;
        const uint32_t st = sbase + (cn % GSTAGES) * STAGE_BYTES;
#pragma unroll
        for (int s = 0; s < 8; s++) {
            const int idx = tid + s * 256;
            const int sub = idx >> 9;            // 0:Ah 1:Al 2:Bh 3:Bl
            const int w   = idx & 511;
            const int row = w >> 2, g = w & 3;
            const uint32_t dst = st + sub * 8192 + SWZ64((uint32_t)(row * 64 + g * 16));
            const __nv_bfloat16* src =
                ((sub & 2) ? Bg : Ag) + (size_t)row * 2048 + ((sub & 1) ? 1024 : 0) + kc + g * 8;
            CP_ASYNC16(dst, (const void*)src);
        }
        CP_COMMIT();
    };

    load_chunk(0);
    load_chunk(1);

    for (int c = 0; c < GEMM_NCHUNK; c++) {
        if (c == GEMM_NCHUNK - 1) CP_WAIT0(); else CP_WAIT1();
        __syncthreads();
        if (c + 2 < GEMM_NCHUNK) load_chunk(c + 2);

        const uint32_t st  = sbase + (c % GSTAGES) * STAGE_BYTES;
        const uint32_t Ahs = st;
        const uint32_t Als = st + 8192;
        const uint32_t Bhs = st + 16384;
        const uint32_t Bls = st + 24576;
#pragma unroll
        for (int ks = 0; ks < 2; ks++) {
            uint32_t ah[2][4], al[2][4];
            const int acb = ks * 32 + (quad >> 1) * 16;
            const int bcb = ks * 32 + (quad & 1) * 16;
#pragma unroll
            for (int i = 0; i < 2; i++) {
                const int row = wm * 32 + i * 16 + r8 + (quad & 1) * 8;
                const uint32_t off = SWZ64((uint32_t)(row * 64 + acb));
                ldm_x4(ah[i], Ahs + off);
                ldm_x4(al[i], Als + off);
            }
#pragma unroll
            for (int j = 0; j < 4; j++) {
                uint32_t bh[4], bl[4];
                const int row = wn * 64 + j * 16 + r8 + (quad >> 1) * 8;
                const uint32_t off = SWZ64((uint32_t)(row * 64 + bcb));
                ldm_x4(bh, Bhs + off);
                ldm_x4(bl, Bls + off);
#pragma unroll
                for (int i = 0; i < 2; i++) {
                    mma16816(acc[i][2*j],   ah[i][0], ah[i][1], ah[i][2], ah[i][3], bh[0], bh[1]);
                    mma16816(acc[i][2*j],   ah[i][0], ah[i][1], ah[i][2], ah[i][3], bl[0], bl[1]);
                    mma16816(acc[i][2*j],   al[i][0], al[i][1], al[i][2], al[i][3], bh[0], bh[1]);
                    mma16816(acc[i][2*j+1], ah[i][0], ah[i][1], ah[i][2], ah[i][3], bh[2], bh[3]);
                    mma16816(acc[i][2*j+1], ah[i][0], ah[i][1], ah[i][2], ah[i][3], bl[2], bl[3]);
                    mma16816(acc[i][2*j+1], al[i][0], al[i][1], al[i][2], al[i][3], bh[2], bh[3]);
                }
            }
        }
    }

    const int erow  = lane >> 2;        // fragment row within 16-row tile
    const int ecol2 = (lane & 3) * 2;   // fragment col pair base

    if (proj) {
        // plain fp32 epilogue -> harness output
#pragma unroll
        for (int i = 0; i < 2; i++)
#pragma unroll
            for (int f = 0; f < 8; f++) {
                float* p0 = outp + (size_t)(m0 + wm * 32 + i * 16 + erow) * 1024
                              + n0 + wn * 64 + f * 8 + ecol2;
                *(float2*)p0            = make_float2(acc[i][f][0], acc[i][f][1]);
                *(float2*)(p0 + 8*1024) = make_float2(acc[i][f][2], acc[i][f][3]);
            }
        return;
    }

    const int h = (n0 + wn * 64) >> 6;                 // head index 0..15
    __nv_bfloat16* OH = (z == 0) ? g_qh : (z == 1) ? g_kh : g_vh;
    __nv_bfloat16* OL = (z == 0) ? g_ql : (z == 1) ? g_kl : g_vl;

    if (z == 2) {
        // V: bf16 hi/lo split only
#pragma unroll
        for (int i = 0; i < 2; i++)
#pragma unroll
            for (int f = 0; f < 8; f++) {
                const int t0 = m0 + wm * 32 + i * 16 + erow;
                const size_t o0 = (size_t)t0 * DIM_ + h * HD + f * 8 + ecol2;
                const size_t o1 = o0 + 8 * DIM_;
                __nv_bfloat16 h0 = __float2bfloat16(acc[i][f][0]);
                __nv_bfloat16 h1 = __float2bfloat16(acc[i][f][1]);
                __nv_bfloat16 h2 = __float2bfloat16(acc[i][f][2]);
                __nv_bfloat16 h3 = __float2bfloat16(acc[i][f][3]);
                *(uint32_t*)(OH + o0) = pack_bf16(h0, h1);
                *(uint32_t*)(OH + o1) = pack_bf16(h2, h3);
                *(uint32_t*)(OL + o0) = pack_bf16(
                    __float2bfloat16(acc[i][f][0] - __bfloat162float(h0)),
                    __float2bfloat16(acc[i][f][1] - __bfloat162float(h1)));
                *(uint32_t*)(OL + o1) = pack_bf16(
                    __float2bfloat16(acc[i][f][2] - __bfloat162float(h2)),
                    __float2bfloat16(acc[i][f][3] - __bfloat162float(h3)));
            }
        return;
    }

    // Q/K: cosine-norm + s_eff + rotary + split
    float sc[8][2];
#pragma unroll
    for (int f = 0; f < 8; f++) {
        sc[f][0] = s_qk[h * HD + f * 8 + ecol2]     * 32.0f;
        sc[f][1] = s_qk[h * HD + f * 8 + ecol2 + 1] * 32.0f;
    }
#pragma unroll
    for (int i = 0; i < 2; i++)
#pragma unroll
    for (int half = 0; half < 2; half++) {
        const int t  = m0 + wm * 32 + i * 16 + erow + half * 8;
        const int qo = half * 2;
        float w[8][2];
        float ss = 0.0f;
#pragma unroll
        for (int f = 0; f < 8; f++) {
            w[f][0] = acc[i][f][qo];
            w[f][1] = acc[i][f][qo + 1];
            ss += w[f][0] * w[f][0] + w[f][1] * w[f][1];
        }
        ss += __shfl_xor_sync(0xffffffffu, ss, 1);
        ss += __shfl_xor_sync(0xffffffffu, ss, 2);
        const float rn = rsqrtf(ss + 1e-12f);
#pragma unroll
        for (int f = 0; f < 8; f++) {
            w[f][0] *= rn * sc[f][0];
            w[f][1] *= rn * sc[f][1];
        }
        // rope: pairs (col j, col j+32) = (f, f+4), same e
#pragma unroll
        for (int f = 0; f < 2; f++)
#pragma unroll
            for (int e = 0; e < 2; e++) {
                const int j = f * 8 + ecol2 + e;     // 0..15
                float sth, cth;
                sincosf((float)t * FREQ16[j], &sth, &cth);
                float y1 = w[f][e] * cth + w[f + 4][e] * sth;
                float y2 = w[f + 4][e] * cth - w[f][e] * sth;
                w[f][e] = y1; w[f + 4][e] = y2;
            }
        // f=2,3 (cols 16..31): c=1,s=0 -> identity
#pragma unroll
        for (int f = 0; f < 8; f++) {
            const size_t off = (size_t)t * DIM_ + h * HD + f * 8 + ecol2;
            __nv_bfloat16 h0 = __float2bfloat16(w[f][0]);
            __nv_bfloat16 h1 = __float2bfloat16(w[f][1]);
            *(uint32_t*)(OH + off) = pack_bf16(h0, h1);
            *(uint32_t*)(OL + off) = pack_bf16(
                __float2bfloat16(w[f][0] - __bfloat162float(h0)),
                __float2bfloat16(w[f][1] - __bfloat162float(h1)));
        }
    }
}

// ---------------- pipelined flash attention, triangle-paired CTAs ---------------
// grid (16, 16): CTA bx handles qb = 31-bx then qb = bx -> 33 key-tiles each,
// perfectly balanced, 256 equal CTAs (single wave at 2/SM).
#define ATT_STAGE 32768
#define ATT_SMEM  (2 * ATT_STAGE)

__global__ __launch_bounds__(128) void attn_mma()
{
    extern __shared__ char sma[];
    const uint32_t sbase = smem_u32(sma);

    const int bx   = blockIdx.x;
    const int h    = blockIdx.y;
    const int tid  = threadIdx.x;
    const int wid  = tid >> 5;
    const int lane = tid & 31;
    const int lr   = lane >> 2;
    const int lc   = lane & 3;

    const __nv_bfloat16* GKh0 = g_kh + h * HD;
    const __nv_bfloat16* GKl0 = g_kl + h * HD;
    const __nv_bfloat16* GVh0 = g_vh + h * HD;
    const __nv_bfloat16* GVl0 = g_vl + h * HD;

    auto load_tiles = [&](int kb, int stage) {
        const uint32_t sb = sbase + stage * ATT_STAGE;
        const size_t gbase = (size_t)(kb * 64) * DIM_;
#pragma unroll
        for (int i = 0; i < 4; i++) {
            const int idx = tid + i * 128;
            const int row = idx >> 3, g = idx & 7;
            const uint32_t off = SWZ128((uint32_t)(row * 128 + g * 16));
            const size_t goff = gbase + (size_t)row * DIM_ + g * 8;
            CP_ASYNC16(sb + off,          (const void*)(GKh0 + goff));
            CP_ASYNC16(sb + 8192 + off,   (const void*)(GKl0 + goff));
            CP_ASYNC16(sb + 16384 + off,  (const void*)(GVh0 + goff));
            CP_ASYNC16(sb + 24576 + off,  (const void*)(GVl0 + goff));
        }
        CP_COMMIT();
    };

    const int l7  = lane & 7;
    const int lk8 = (lane >> 4) * 8;
    const int ld8 = ((lane >> 3) & 1) * 8;

    for (int pass = 0; pass < 2; pass++) {
        const int qb = pass ? bx : 31 - bx;

        __syncthreads();   // all warps done with smem from previous pass
        load_tiles(0, 0);

        // hoist Q A-fragments (hi/lo) from global
        const size_t qrow0 = (size_t)(qb * 64 + wid * 16 + lr) * DIM_ + h * HD;
        const size_t qrow8 = qrow0 + 8 * DIM_;
        uint32_t qa_h[4][4], qa_l[4][4];
#pragma unroll
        for (int t = 0; t < 4; t++) {
            const int c0 = t * 16 + 2 * lc;
            qa_h[t][0] = *(const uint32_t*)(g_qh + qrow0 + c0);
            qa_h[t][1] = *(const uint32_t*)(g_qh + qrow8 + c0);
            qa_h[t][2] = *(const uint32_t*)(g_qh + qrow0 + c0 + 8);
            qa_h[t][3] = *(const uint32_t*)(g_qh + qrow8 + c0 + 8);
            qa_l[t][0] = *(const uint32_t*)(g_ql + qrow0 + c0);
            qa_l[t][1] = *(const uint32_t*)(g_ql + qrow8 + c0);
            qa_l[t][2] = *(const uint32_t*)(g_ql + qrow0 + c0 + 8);
            qa_l[t][3] = *(const uint32_t*)(g_ql + qrow8 + c0 + 8);
        }

        float ofr[8][4];
#pragma unroll
        for (int j = 0; j < 8; j++)
#pragma unroll
            for (int q = 0; q < 4; q++) ofr[j][q] = 0.0f;
        float m0 = -1e30f, m1 = -1e30f, l0 = 0.0f, l1 = 0.0f;

        const int gr0 = qb * 64 + wid * 16 + lr;
        const int gr8 = gr0 + 8;

        for (int kb = 0; kb <= qb; kb++) {
            CP_WAIT0();
            __syncthreads();
            if (kb < qb) load_tiles(kb + 1, (kb + 1) & 1);

            const uint32_t sb  = sbase + (kb & 1) * ATT_STAGE;
            const uint32_t Khs = sb;
            const uint32_t Kls = sb + 8192;
            const uint32_t Vhs = sb + 16384;
            const uint32_t Vls = sb + 24576;

            float sfr[8][4];
#pragma unroll
            for (int j = 0; j < 8; j++)
#pragma unroll
                for (int q = 0; q < 4; q++) sfr[j][q] = 0.0f;

#pragma unroll
            for (int t = 0; t < 4; t++) {
#pragma unroll
                for (int jp = 0; jp < 4; jp++) {
                    const uint32_t off = SWZ128((uint32_t)((jp * 16 + lk8 + l7) * 128
                                                           + (t * 16 + ld8) * 2));
                    uint32_t kh[4], kl[4];
                    ldm_x4(kh, Khs + off);
                    ldm_x4(kl, Kls + off);
                    mma16816(sfr[2*jp],   qa_h[t][0], qa_h[t][1], qa_h[t][2], qa_h[t][3], kh[0], kh[1]);
                    mma16816(sfr[2*jp],   qa_h[t][0], qa_h[t][1], qa_h[t][2], qa_h[t][3], kl[0], kl[1]);
                    mma16816(sfr[2*jp],   qa_l[t][0], qa_l[t][1], qa_l[t][2], qa_l[t][3], kh[0], kh[1]);
                    mma16816(sfr[2*jp+1], qa_h[t][0], qa_h[t][1], qa_h[t][2], qa_h[t][3], kh[2], kh[3]);
                    mma16816(sfr[2*jp+1], qa_h[t][0], qa_h[t][1], qa_h[t][2], qa_h[t][3], kl[2], kl[3]);
                    mma16816(sfr[2*jp+1], qa_l[t][0], qa_l[t][1], qa_l[t][2], qa_l[t][3], kh[2], kh[3]);
                }
            }

            const bool diag = (kb == qb);
#pragma unroll
            for (int j = 0; j < 8; j++) {
                const int gc = kb * 64 + j * 8 + 2 * lc;
                float v0 = sfr[j][0] * ATTN_SCALE;
                float v1 = sfr[j][1] * ATTN_SCALE;
                float v2 = sfr[j][2] * ATTN_SCALE;
                float v3 = sfr[j][3] * ATTN_SCALE;
                if (diag) {
                    if (gc     > gr0) v0 = -1e30f;
                    if (gc + 1 > gr0) v1 = -1e30f;
                    if (gc     > gr8) v2 = -1e30f;
                    if (gc + 1 > gr8) v3 = -1e30f;
                }
                sfr[j][0] = v0; sfr[j][1] = v1; sfr[j][2] = v2; sfr[j][3] = v3;
            }

            float mx0 = -1e30f, mx1 = -1e30f;
#pragma unroll
            for (int j = 0; j < 8; j++) {
                mx0 = fmaxf(mx0, fmaxf(sfr[j][0], sfr[j][1]));
                mx1 = fmaxf(mx1, fmaxf(sfr[j][2], sfr[j][3]));
            }
            mx0 = fmaxf(mx0, __shfl_xor_sync(0xffffffffu, mx0, 1));
            mx0 = fmaxf(mx0, __shfl_xor_sync(0xffffffffu, mx0, 2));
            mx1 = fmaxf(mx1, __shfl_xor_sync(0xffffffffu, mx1, 1));
            mx1 = fmaxf(mx1, __shfl_xor_sync(0xffffffffu, mx1, 2));
            const float mn0 = fmaxf(m0, mx0);
            const float mn1 = fmaxf(m1, mx1);
            const float cor0 = __expf(m0 - mn0);
            const float cor1 = __expf(m1 - mn1);
            m0 = mn0; m1 = mn1;
            float s0 = 0.0f, s1 = 0.0f;
#pragma unroll
            for (int j = 0; j < 8; j++) {
                sfr[j][0] = __expf(sfr[j][0] - mn0);
                sfr[j][1] = __expf(sfr[j][1] - mn0);
                sfr[j][2] = __expf(sfr[j][2] - mn1);
                sfr[j][3] = __expf(sfr[j][3] - mn1);
                s0 += sfr[j][0] + sfr[j][1];
                s1 += sfr[j][2] + sfr[j][3];
            }
            s0 += __shfl_xor_sync(0xffffffffu, s0, 1);
            s0 += __shfl_xor_sync(0xffffffffu, s0, 2);
            s1 += __shfl_xor_sync(0xffffffffu, s1, 1);
            s1 += __shfl_xor_sync(0xffffffffu, s1, 2);
            l0 = l0 * cor0 + s0;
            l1 = l1 * cor1 + s1;

#pragma unroll
            for (int j = 0; j < 8; j++) {
                ofr[j][0] *= cor0; ofr[j][1] *= cor0;
                ofr[j][2] *= cor1; ofr[j][3] *= cor1;
            }

#pragma unroll
            for (int u = 0; u < 4; u++) {
                __nv_bfloat16 b00 = __float2bfloat16(sfr[2*u][0]);
                __nv_bfloat16 b01 = __float2bfloat16(sfr[2*u][1]);
                __nv_bfloat16 b02 = __float2bfloat16(sfr[2*u][2]);
                __nv_bfloat16 b03 = __float2bfloat16(sfr[2*u][3]);
                __nv_bfloat16 b10 = __float2bfloat16(sfr[2*u+1][0]);
                __nv_bfloat16 b11 = __float2bfloat16(sfr[2*u+1][1]);
                __nv_bfloat16 b12 = __float2bfloat16(sfr[2*u+1][2]);
                __nv_bfloat16 b13 = __float2bfloat16(sfr[2*u+1][3]);
                uint32_t pah0 = pack_bf16(b00, b01);
                uint32_t pah1 = pack_bf16(b02, b03);
                uint32_t pah2 = pack_bf16(b10, b11);
                uint32_t pah3 = pack_bf16(b12, b13);
                uint32_t pal0 = pack_bf16(__float2bfloat16(sfr[2*u][0]   - __bfloat162float(b00)),
                                          __float2bfloat16(sfr[2*u][1]   - __bfloat162float(b01)));
                uint32_t pal1 = pack_bf16(__float2bfloat16(sfr[2*u][2]   - __bfloat162float(b02)),
                                          __float2bfloat16(sfr[2*u][3]   - __bfloat162float(b03)));
                uint32_t pal2 = pack_bf16(__float2bfloat16(sfr[2*u+1][0] - __bfloat162float(b10)),
                                          __float2bfloat16(sfr[2*u+1][1] - __bfloat162float(b11)));
                uint32_t pal3 = pack_bf16(__float2bfloat16(sfr[2*u+1][2] - __bfloat162float(b12)),
                                          __float2bfloat16(sfr[2*u+1][3] - __bfloat162float(b13)));
#pragma unroll
                for (int jp = 0; jp < 4; jp++) {
                    const uint32_t off = SWZ128((uint32_t)((u * 16 + ld8 + l7) * 128
                                                           + (jp * 16 + lk8) * 2));
                    uint32_t vh[4], vl[4];
                    ldm_x4_t(vh, Vhs + off);
                    ldm_x4_t(vl, Vls + off);
                    mma16816(ofr[2*jp],   pah0, pah1, pah2, pah3, vh[0], vh[1]);
                    mma16816(ofr[2*jp],   pah0, pah1, pah2, pah3, vl[0], vl[1]);
                    mma16816(ofr[2*jp],   pal0, pal1, pal2, pal3, vh[0], vh[1]);
                    mma16816(ofr[2*jp+1], pah0, pah1, pah2, pah3, vh[2], vh[3]);
                    mma16816(ofr[2*jp+1], pah0, pah1, pah2, pah3, vl[2], vl[3]);
                    mma16816(ofr[2*jp+1], pal0, pal1, pal2, pal3, vh[2], vh[3]);
                }
            }
        }

        // epilogue: write hi/lo bf16 split of (O/l) into g_ybig
        const float inv0 = 1.0f / l0;
        const float inv1 = 1.0f / l1;
        __nv_bfloat16* Y0 = g_ybig + (size_t)gr0 * 2048 + h * HD;
        __nv_bfloat16* Y8 = g_ybig + (size_t)gr8 * 2048 + h * HD;
#pragma unroll
        for (int j2 = 0; j2 < 8; j2++) {
            const int cc = j2 * 8 + 2 * lc;
            float y0 = ofr[j2][0] * inv0, y1 = ofr[j2][1] * inv0;
            float y2 = ofr[j2][2] * inv1, y3 = ofr[j2][3] * inv1;
            __nv_bfloat16 h0 = __float2bfloat16(y0), h1 = __float2bfloat16(y1);
            __nv_bfloat16 h2 = __float2bfloat16(y2), h3 = __float2bfloat16(y3);
            *(uint32_t*)(Y0 + cc)        = pack_bf16(h0, h1);
            *(uint32_t*)(Y8 + cc)        = pack_bf16(h2, h3);
            *(uint32_t*)(Y0 + 1024 + cc) = pack_bf16(__float2bfloat16(y0 - __bfloat162float(h0)),
                                                     __float2bfloat16(y1 - __bfloat162float(h1)));
            *(uint32_t*)(Y8 + 1024 + cc) = pack_bf16(__float2bfloat16(y2 - __bfloat162float(h2)),
                                                     __float2bfloat16(y3 - __bfloat162float(h3)));
        }
    }
}

// ---------------- launcher ------------------------------------------------------
extern "C" void kernel_launch(void* const* d_in, const int* in_sizes, int n_in,
                              void* d_out, int out_size)
{
    const float* x    = (const float*)d_in[0];
    const float* Wq   = (const float*)d_in[1];
    const float* Wk   = (const float*)d_in[2];
    const float* Wv   = (const float*)d_in[3];
    const float* Wo   = (const float*)d_in[4];
    const float* s_qk = (const float*)d_in[5];
    float* out = (float*)d_out;

    cudaFuncSetAttribute(gemm_mma, cudaFuncAttributeMaxDynamicSharedMemorySize,
                         GEMM_SMEM);
    cudaFuncSetAttribute(attn_mma, cudaFuncAttributeMaxDynamicSharedMemorySize,
                         ATT_SMEM);

    // operand prep
    split_kernel<<<2048, 256>>>(x);
    wconv_kernel<<<dim3(32, 32, 4), 256>>>(Wq, Wk, Wv, Wo);

    // QKV projections with fused cosine-norm + rope + bf16-split epilogue
    gemm_mma<<<dim3(8, 16, 3), 256, GEMM_SMEM>>>(0, nullptr, s_qk);

    // triangle-paired flash attention (epilogue feeds g_ybig)
    attn_mma<<<dim3(16, NHEAD), 128, ATT_SMEM>>>();

    // output projection
    gemm_mma<<<dim3(8, 16, 1), 256, GEMM_SMEM>>>(1, out, nullptr);
}